// round 1
// baseline (speedup 1.0000x reference)
#include <cuda_runtime.h>
#include <math.h>

#define Bsz   2
#define Seq   2048
#define Dim   1024
#define NHead 16
#define HDim  64

// Scratch (static device globals — allocation-guard safe)
__device__ float g_qkv[Bsz * Seq * 3 * Dim];  // [b, s, 3*Dim]  q|k|v
__device__ float g_y  [Bsz * Seq * Dim];      // attention output [b, s, h*64+d]

// ---------------------------------------------------------------------------
// C[M][N] = A[M][K] @ B[N][K]^T   (both row-major, K contiguous), ldc = N
// 64x64 block tile, BK=16, 256 threads, 4x4 register micro-tile.
// ---------------------------------------------------------------------------
__global__ __launch_bounds__(256) void sgemm_nt(const float* __restrict__ A,
                                                const float* __restrict__ Bm,
                                                float* __restrict__ C,
                                                int M, int N, int K) {
    __shared__ float As[16][68];   // [k][m], padded stride 68 (16B-aligned rows)
    __shared__ float Bs[16][68];   // [k][n]
    const int t  = threadIdx.x;
    const int tx = t & 15, ty = t >> 4;
    const int bm = blockIdx.y * 64, bn = blockIdx.x * 64;

    const int lr  = t >> 2;          // 0..63 (row to load)
    const int lc  = (t & 3) << 2;    // 0,4,8,12 (k offset, float4)
    const float* Aptr = A + (bm + lr) * K + lc;
    const float* Bptr = Bm + (bn + lr) * K + lc;

    float acc[4][4] = {};

    for (int k0 = 0; k0 < K; k0 += 16) {
        float4 va = *(const float4*)(Aptr + k0);
        float4 vb = *(const float4*)(Bptr + k0);
        As[lc + 0][lr] = va.x; As[lc + 1][lr] = va.y;
        As[lc + 2][lr] = va.z; As[lc + 3][lr] = va.w;
        Bs[lc + 0][lr] = vb.x; Bs[lc + 1][lr] = vb.y;
        Bs[lc + 2][lr] = vb.z; Bs[lc + 3][lr] = vb.w;
        __syncthreads();
#pragma unroll
        for (int k = 0; k < 16; k++) {
            float4 a4 = *(const float4*)&As[k][ty * 4];
            float4 b4 = *(const float4*)&Bs[k][tx * 4];
            float av[4] = {a4.x, a4.y, a4.z, a4.w};
            float bv[4] = {b4.x, b4.y, b4.z, b4.w};
#pragma unroll
            for (int i = 0; i < 4; i++)
#pragma unroll
                for (int j = 0; j < 4; j++)
                    acc[i][j] += av[i] * bv[j];
        }
        __syncthreads();
    }
#pragma unroll
    for (int i = 0; i < 4; i++) {
        float4 o = make_float4(acc[i][0], acc[i][1], acc[i][2], acc[i][3]);
        *(float4*)&C[(bm + ty * 4 + i) * N + bn + tx * 4] = o;
    }
}

// ---------------------------------------------------------------------------
// RoPE in place on q and k sections of g_qkv.
// p in [0, Dim/2): head h = p/32, pair j = p%32; flat dim offset = 2*p.
// freqs_cis: [Seq][32][2] (cos, sin)
// ---------------------------------------------------------------------------
__global__ __launch_bounds__(256) void rope_kernel(const float* __restrict__ fc) {
    int idx = blockIdx.x * blockDim.x + threadIdx.x;
    const int total = Bsz * Seq * (Dim / 2);
    if (idx >= total) return;
    int p = idx % (Dim / 2);
    int s = (idx / (Dim / 2)) % Seq;
    int b = idx / (Seq * (Dim / 2));
    int j = p & 31;
    float c  = fc[s * 64 + j * 2 + 0];
    float sn = fc[s * 64 + j * 2 + 1];
    int base = (b * Seq + s) * 3 * Dim;
    int off  = p * 2;

    float* q = &g_qkv[base + off];
    float xr = q[0], xi = q[1];
    q[0] = xr * c - xi * sn;
    q[1] = xi * c + xr * sn;

    float* kk = &g_qkv[base + Dim + off];
    xr = kk[0]; xi = kk[1];
    kk[0] = xr * c - xi * sn;
    kk[1] = xi * c + xr * sn;
}

// ---------------------------------------------------------------------------
// Flash attention, fp32, causal. Block = (q-tile of 64 rows) x (b*h).
// 256 threads: 16x16 grid, thread owns 4 q-rows x 4 cols (kc or d).
// ---------------------------------------------------------------------------
__device__ __forceinline__ float redmax16(float v) {
    v = fmaxf(v, __shfl_xor_sync(0xffffffffu, v, 1));
    v = fmaxf(v, __shfl_xor_sync(0xffffffffu, v, 2));
    v = fmaxf(v, __shfl_xor_sync(0xffffffffu, v, 4));
    v = fmaxf(v, __shfl_xor_sync(0xffffffffu, v, 8));
    return v;
}
__device__ __forceinline__ float redsum16(float v) {
    v += __shfl_xor_sync(0xffffffffu, v, 1);
    v += __shfl_xor_sync(0xffffffffu, v, 2);
    v += __shfl_xor_sync(0xffffffffu, v, 4);
    v += __shfl_xor_sync(0xffffffffu, v, 8);
    return v;
}

#define ATTN_SMEM_BYTES (4 * 64 * 68 * 4)

__global__ __launch_bounds__(256) void attn_kernel() {
    extern __shared__ float sm[];
    float (*Qs)[68] = (float(*)[68])(sm + 0 * 64 * 68);  // [d][qr]
    float (*Ks)[68] = (float(*)[68])(sm + 1 * 64 * 68);  // [d][kc]
    float (*Ps)[68] = (float(*)[68])(sm + 2 * 64 * 68);  // [qr][kc]
    float (*Vs)[68] = (float(*)[68])(sm + 3 * 64 * 68);  // [kc][d]

    const int t  = threadIdx.x;
    const int tx = t & 15, ty = t >> 4;
    const int qt = blockIdx.x;               // q tile (64 rows)
    const int bh = blockIdx.y;
    const int b  = bh / NHead, h = bh % NHead;
    const int qkv_b = b * Seq * 3 * Dim;

    const int lr  = t >> 2;                  // 0..63
    const int lc4 = (t & 3) << 2;            // 0,4,8,12

    // load Q tile (transposed to [d][qr])
#pragma unroll
    for (int c = 0; c < 4; c++) {
        int d = lc4 + c * 16;
        float4 v = *(const float4*)&g_qkv[qkv_b + (qt * 64 + lr) * 3 * Dim + h * HDim + d];
        Qs[d + 0][lr] = v.x; Qs[d + 1][lr] = v.y;
        Qs[d + 2][lr] = v.z; Qs[d + 3][lr] = v.w;
    }

    float m[4], l[4], acc[4][4];
#pragma unroll
    for (int i = 0; i < 4; i++) {
        m[i] = -1e30f; l[i] = 0.f;
#pragma unroll
        for (int j = 0; j < 4; j++) acc[i][j] = 0.f;
    }

    for (int kt = 0; kt <= qt; kt++) {
        // load K (transposed) and V tiles
#pragma unroll
        for (int c = 0; c < 4; c++) {
            int d = lc4 + c * 16;
            int row = qkv_b + (kt * 64 + lr) * 3 * Dim + h * HDim + d;
            float4 kv = *(const float4*)&g_qkv[row + Dim];
            Ks[d + 0][lr] = kv.x; Ks[d + 1][lr] = kv.y;
            Ks[d + 2][lr] = kv.z; Ks[d + 3][lr] = kv.w;
            float4 vv = *(const float4*)&g_qkv[row + 2 * Dim];
            *(float4*)&Vs[lr][d] = vv;
        }
        __syncthreads();

        // S = Q @ K^T  (thread: 4 q-rows x 4 k-cols)
        float s[4][4] = {};
#pragma unroll 8
        for (int d = 0; d < 64; d++) {
            float4 a4 = *(const float4*)&Qs[d][ty * 4];
            float4 b4 = *(const float4*)&Ks[d][tx * 4];
            float av[4] = {a4.x, a4.y, a4.z, a4.w};
            float bv[4] = {b4.x, b4.y, b4.z, b4.w};
#pragma unroll
            for (int i = 0; i < 4; i++)
#pragma unroll
                for (int j = 0; j < 4; j++)
                    s[i][j] += av[i] * bv[j];
        }

        // scale + causal mask (diagonal tile only; tiles are aligned)
        if (kt == qt) {
#pragma unroll
            for (int i = 0; i < 4; i++)
#pragma unroll
                for (int j = 0; j < 4; j++)
                    s[i][j] = (tx * 4 + j <= ty * 4 + i) ? s[i][j] * 0.125f : -1e30f;
        } else {
#pragma unroll
            for (int i = 0; i < 4; i++)
#pragma unroll
                for (int j = 0; j < 4; j++)
                    s[i][j] *= 0.125f;
        }

        // online softmax
#pragma unroll
        for (int i = 0; i < 4; i++) {
            float mt = fmaxf(fmaxf(s[i][0], s[i][1]), fmaxf(s[i][2], s[i][3]));
            mt = redmax16(mt);
            float nm = fmaxf(m[i], mt);
            float corr = __expf(m[i] - nm);
#pragma unroll
            for (int j = 0; j < 4; j++) s[i][j] = __expf(s[i][j] - nm);
            float rs = s[i][0] + s[i][1] + s[i][2] + s[i][3];
            rs = redsum16(rs);
            l[i] = l[i] * corr + rs;
#pragma unroll
            for (int j = 0; j < 4; j++) acc[i][j] *= corr;
            m[i] = nm;
        }

        // store P [qr][kc] (float4 rows, no transpose -> conflict-free)
#pragma unroll
        for (int i = 0; i < 4; i++) {
            float4 p4 = make_float4(s[i][0], s[i][1], s[i][2], s[i][3]);
            *(float4*)&Ps[ty * 4 + i][tx * 4] = p4;
        }
        __syncthreads();

        // O += P @ V  (thread: 4 q-rows x 4 dims)
#pragma unroll 8
        for (int kc = 0; kc < 64; kc++) {
            float a0 = Ps[ty * 4 + 0][kc];
            float a1 = Ps[ty * 4 + 1][kc];
            float a2 = Ps[ty * 4 + 2][kc];
            float a3 = Ps[ty * 4 + 3][kc];
            float4 b4 = *(const float4*)&Vs[kc][tx * 4];
            float bv[4] = {b4.x, b4.y, b4.z, b4.w};
            float av[4] = {a0, a1, a2, a3};
#pragma unroll
            for (int i = 0; i < 4; i++)
#pragma unroll
                for (int j = 0; j < 4; j++)
                    acc[i][j] += av[i] * bv[j];
        }
        __syncthreads();
    }

    // write y[b, qt*64+qr, h*64 + d]
#pragma unroll
    for (int i = 0; i < 4; i++) {
        float inv = 1.0f / l[i];
        float4 o = make_float4(acc[i][0] * inv, acc[i][1] * inv,
                               acc[i][2] * inv, acc[i][3] * inv);
        *(float4*)&g_y[(b * Seq + qt * 64 + ty * 4 + i) * Dim + h * HDim + tx * 4] = o;
    }
}

// ---------------------------------------------------------------------------
extern "C" void kernel_launch(void* const* d_in, const int* in_sizes, int n_in,
                              void* d_out, int out_size) {
    const float* x    = (const float*)d_in[0];
    const float* fc   = (const float*)d_in[1];
    // d_in[2] = mask (bool) — causality is structural, unused
    const float* wqkv = (const float*)d_in[3];
    const float* wo   = (const float*)d_in[4];
    float* out = (float*)d_out;

    float* qkv_ptr = nullptr;
    float* y_ptr   = nullptr;
    cudaGetSymbolAddress((void**)&qkv_ptr, g_qkv);
    cudaGetSymbolAddress((void**)&y_ptr, g_y);

    static int smem_set = 0;
    cudaFuncSetAttribute(attn_kernel, cudaFuncAttributeMaxDynamicSharedMemorySize,
                         ATTN_SMEM_BYTES);
    (void)smem_set;

    const int M = Bsz * Seq;  // 4096

    // 1) QKV = X @ Wqkv^T   [4096 x 3072]
    {
        dim3 grid(3 * Dim / 64, M / 64);
        sgemm_nt<<<grid, 256>>>(x, wqkv, qkv_ptr, M, 3 * Dim, Dim);
    }
    // 2) RoPE on q, k
    {
        int total = Bsz * Seq * (Dim / 2);
        rope_kernel<<<(total + 255) / 256, 256>>>(fc);
    }
    // 3) attention -> g_y
    {
        dim3 grid(Seq / 64, Bsz * NHead);
        attn_kernel<<<grid, 256, ATTN_SMEM_BYTES>>>();
    }
    // 4) out = Y @ Wo^T   [4096 x 1024]
    {
        dim3 grid(Dim / 64, M / 64);
        sgemm_nt<<<grid, 256>>>(y_ptr, wo, out, M, Dim, Dim);
    }
}

// round 3
// speedup vs baseline: 1.5419x; 1.5419x over previous
#include <cuda_runtime.h>
#include <cuda_bf16.h>
#include <cstdint>
#include <math.h>

#define Bsz   2
#define Seq   2048
#define Dim   1024
#define NHead 16
#define HDim  64

// Scratch (static device globals — allocation-guard safe)
__device__ float g_qkv[Bsz * Seq * 3 * Dim];  // [b, s, 3*Dim]  q|k|v
__device__ float g_y  [Bsz * Seq * Dim];      // attention output

// ===========================================================================
// mma.sync helpers (sm_80+, works under compute_103 non-'a' target)
// ===========================================================================
__device__ __forceinline__ void ldm_x4(uint32_t* r, uint32_t addr) {
    asm volatile("ldmatrix.sync.aligned.m8n8.x4.shared.b16 {%0,%1,%2,%3}, [%4];"
                 : "=r"(r[0]), "=r"(r[1]), "=r"(r[2]), "=r"(r[3]) : "r"(addr));
}
__device__ __forceinline__ void mma_bf16(float* d, const uint32_t* a,
                                         const uint32_t* b) {
    asm volatile(
        "mma.sync.aligned.m16n8k16.row.col.f32.bf16.bf16.f32 "
        "{%0,%1,%2,%3}, {%4,%5,%6,%7}, {%8,%9}, {%0,%1,%2,%3};"
        : "+f"(d[0]), "+f"(d[1]), "+f"(d[2]), "+f"(d[3])
        : "r"(a[0]), "r"(a[1]), "r"(a[2]), "r"(a[3]), "r"(b[0]), "r"(b[1]));
}
__device__ __forceinline__ uint32_t smem_u32(const void* p) {
    uint32_t a;
    asm("{ .reg .u64 t; cvta.to.shared.u64 t, %1; cvt.u32.u64 %0, t; }"
        : "=r"(a) : "l"(p));
    return a;
}
__device__ __forceinline__ uint32_t pk_bf2(__nv_bfloat16 a, __nv_bfloat16 b) {
    __nv_bfloat162 t(a, b);
    return *reinterpret_cast<uint32_t*>(&t);
}
// split float4 into hi/lo bf16 pairs (uint2 each)
__device__ __forceinline__ void cvt_split4(float4 v, uint2* hi, uint2* lo) {
    __nv_bfloat16 hx = __float2bfloat16(v.x), hy = __float2bfloat16(v.y);
    __nv_bfloat16 hz = __float2bfloat16(v.z), hw = __float2bfloat16(v.w);
    *hi = make_uint2(pk_bf2(hx, hy), pk_bf2(hz, hw));
    *lo = make_uint2(
        pk_bf2(__float2bfloat16(v.x - __bfloat162float(hx)),
               __float2bfloat16(v.y - __bfloat162float(hy))),
        pk_bf2(__float2bfloat16(v.z - __bfloat162float(hz)),
               __float2bfloat16(v.w - __bfloat162float(hw))));
}

// ===========================================================================
// HMMA GEMM: C[M][N] = A[M][K=1024] @ B[N][K=1024]^T (fp32 in/out)
// 3-term bf16 split, fp32 register accumulators.
// 128x128x32 CTA tile, 256 threads, warp tile 64x32. grid=(N/128, M/128)
// ===========================================================================
#define GK   1024
#define BK   32
#define LDSS 40   // padded bf16 row stride (80B): conflict-free ldmatrix

__global__ __launch_bounds__(256) void gemm_mma(const float* __restrict__ A,
                                                const float* __restrict__ Bm,
                                                float* __restrict__ C, int N) {
    __shared__ __align__(16) __nv_bfloat16 sAh[128 * LDSS];
    __shared__ __align__(16) __nv_bfloat16 sAl[128 * LDSS];
    __shared__ __align__(16) __nv_bfloat16 sBh[128 * LDSS];
    __shared__ __align__(16) __nv_bfloat16 sBl[128 * LDSS];

    const int t = threadIdx.x;
    const int lane = t & 31, wid = t >> 5;
    const int wm = (wid & 1) * 64;    // warp m offset in tile
    const int wn = (wid >> 1) * 32;   // warp n offset in tile
    const int bm = blockIdx.y * 128, bn = blockIdx.x * 128;

    const uint32_t uAh = smem_u32(sAh), uAl = smem_u32(sAl);
    const uint32_t uBh = smem_u32(sBh), uBl = smem_u32(sBl);

    // global loader mapping: thread t -> rows r0, r0+64; cols c0, c0+16 (float4)
    const int r0 = t >> 2, c0 = (t & 3) * 4;

    float4 ra[4], rb[4];
    float d[4][4][4];
#pragma unroll
    for (int mi = 0; mi < 4; mi++)
#pragma unroll
        for (int nj = 0; nj < 4; nj++)
#pragma unroll
            for (int e = 0; e < 4; e++) d[mi][nj][e] = 0.f;

#pragma unroll
    for (int p = 0; p < 4; p++) {
        int row = r0 + (p >> 1) * 64, col = c0 + (p & 1) * 16;
        ra[p] = *(const float4*)(A + (size_t)(bm + row) * GK + col);
        rb[p] = *(const float4*)(Bm + (size_t)(bn + row) * GK + col);
    }

    for (int it = 0; it < GK / BK; it++) {
        // convert + store current regs to smem
#pragma unroll
        for (int p = 0; p < 4; p++) {
            int row = r0 + (p >> 1) * 64, col = c0 + (p & 1) * 16;
            int off = row * LDSS + col;
            cvt_split4(ra[p], (uint2*)&sAh[off], (uint2*)&sAl[off]);
            cvt_split4(rb[p], (uint2*)&sBh[off], (uint2*)&sBl[off]);
        }
        __syncthreads();

        // prefetch next K-block (LDGs overlap the HMMA below)
        if (it + 1 < GK / BK) {
            const int k0 = (it + 1) * BK;
#pragma unroll
            for (int p = 0; p < 4; p++) {
                int row = r0 + (p >> 1) * 64, col = c0 + (p & 1) * 16;
                ra[p] = *(const float4*)(A + (size_t)(bm + row) * GK + k0 + col);
                rb[p] = *(const float4*)(Bm + (size_t)(bn + row) * GK + k0 + col);
            }
        }

#pragma unroll
        for (int ks = 0; ks < 2; ks++) {
            const int k0 = ks * 16;
            // A fragments (hi & lo)
            uint32_t ah[4][4], al[4][4];
            const int arow = wm + (lane & 15);
            const int acol = k0 + (lane >> 4) * 8;
#pragma unroll
            for (int mi = 0; mi < 4; mi++) {
                uint32_t o = (uint32_t)(((arow + mi * 16) * LDSS + acol) * 2);
                ldm_x4(ah[mi], uAh + o);
                ldm_x4(al[mi], uAl + o);
            }
            // B fragments (hi & lo): x4 loads two n8 tiles at once
            uint32_t bh[2][4], bl[2][4];
            const int brow = wn + (lane & 7) + ((lane & 16) >> 1);
            const int bcol = k0 + ((lane & 8) ? 8 : 0);
#pragma unroll
            for (int nb = 0; nb < 2; nb++) {
                uint32_t o = (uint32_t)(((brow + nb * 16) * LDSS + bcol) * 2);
                ldm_x4(bh[nb], uBh + o);
                ldm_x4(bl[nb], uBl + o);
            }
            // 3-term MMA
#pragma unroll
            for (int mi = 0; mi < 4; mi++)
#pragma unroll
                for (int nj = 0; nj < 4; nj++) {
                    const uint32_t* fh = &bh[nj >> 1][(nj & 1) * 2];
                    const uint32_t* fl = &bl[nj >> 1][(nj & 1) * 2];
                    mma_bf16(d[mi][nj], ah[mi], fh);
                    mma_bf16(d[mi][nj], ah[mi], fl);
                    mma_bf16(d[mi][nj], al[mi], fh);
                }
        }
        __syncthreads();
    }

    // epilogue
#pragma unroll
    for (int mi = 0; mi < 4; mi++)
#pragma unroll
        for (int nj = 0; nj < 4; nj++) {
            int row = bm + wm + mi * 16 + (lane >> 2);
            int col = bn + wn + nj * 8 + (lane & 3) * 2;
            *(float2*)&C[(size_t)row * N + col] =
                make_float2(d[mi][nj][0], d[mi][nj][1]);
            *(float2*)&C[(size_t)(row + 8) * N + col] =
                make_float2(d[mi][nj][2], d[mi][nj][3]);
        }
}

// ===========================================================================
// RoPE in place on q and k sections of g_qkv. freqs_cis: [Seq][32][2]
// ===========================================================================
__global__ __launch_bounds__(256) void rope_kernel(const float* __restrict__ fc) {
    int idx = blockIdx.x * blockDim.x + threadIdx.x;
    const int total = Bsz * Seq * (Dim / 2);
    if (idx >= total) return;
    int p = idx % (Dim / 2);
    int s = (idx / (Dim / 2)) % Seq;
    int b = idx / (Seq * (Dim / 2));
    int j = p & 31;
    float c  = fc[s * 64 + j * 2 + 0];
    float sn = fc[s * 64 + j * 2 + 1];
    int base = (b * Seq + s) * 3 * Dim;
    int off  = p * 2;

    float* q = &g_qkv[base + off];
    float xr = q[0], xi = q[1];
    q[0] = xr * c - xi * sn;
    q[1] = xi * c + xr * sn;

    float* kk = &g_qkv[base + Dim + off];
    xr = kk[0]; xi = kk[1];
    kk[0] = xr * c - xi * sn;
    kk[1] = xi * c + xr * sn;
}

// ===========================================================================
// Flash attention, fp32, causal (unchanged)
// ===========================================================================
__device__ __forceinline__ float redmax16(float v) {
    v = fmaxf(v, __shfl_xor_sync(0xffffffffu, v, 1));
    v = fmaxf(v, __shfl_xor_sync(0xffffffffu, v, 2));
    v = fmaxf(v, __shfl_xor_sync(0xffffffffu, v, 4));
    v = fmaxf(v, __shfl_xor_sync(0xffffffffu, v, 8));
    return v;
}
__device__ __forceinline__ float redsum16(float v) {
    v += __shfl_xor_sync(0xffffffffu, v, 1);
    v += __shfl_xor_sync(0xffffffffu, v, 2);
    v += __shfl_xor_sync(0xffffffffu, v, 4);
    v += __shfl_xor_sync(0xffffffffu, v, 8);
    return v;
}

#define ATTN_SMEM_BYTES (4 * 64 * 68 * 4)

__global__ __launch_bounds__(256) void attn_kernel() {
    extern __shared__ float sm[];
    float (*Qs)[68] = (float(*)[68])(sm + 0 * 64 * 68);
    float (*Ks)[68] = (float(*)[68])(sm + 1 * 64 * 68);
    float (*Ps)[68] = (float(*)[68])(sm + 2 * 64 * 68);
    float (*Vs)[68] = (float(*)[68])(sm + 3 * 64 * 68);

    const int t  = threadIdx.x;
    const int tx = t & 15, ty = t >> 4;
    const int qt = blockIdx.x;
    const int bh = blockIdx.y;
    const int b  = bh / NHead, h = bh % NHead;
    const int qkv_b = b * Seq * 3 * Dim;

    const int lr  = t >> 2;
    const int lc4 = (t & 3) << 2;

#pragma unroll
    for (int c = 0; c < 4; c++) {
        int d = lc4 + c * 16;
        float4 v = *(const float4*)&g_qkv[qkv_b + (qt * 64 + lr) * 3 * Dim + h * HDim + d];
        Qs[d + 0][lr] = v.x; Qs[d + 1][lr] = v.y;
        Qs[d + 2][lr] = v.z; Qs[d + 3][lr] = v.w;
    }

    float m[4], l[4], acc[4][4];
#pragma unroll
    for (int i = 0; i < 4; i++) {
        m[i] = -1e30f; l[i] = 0.f;
#pragma unroll
        for (int j = 0; j < 4; j++) acc[i][j] = 0.f;
    }

    for (int kt = 0; kt <= qt; kt++) {
#pragma unroll
        for (int c = 0; c < 4; c++) {
            int d = lc4 + c * 16;
            int rowoff = qkv_b + (kt * 64 + lr) * 3 * Dim + h * HDim + d;
            float4 kv = *(const float4*)&g_qkv[rowoff + Dim];
            Ks[d + 0][lr] = kv.x; Ks[d + 1][lr] = kv.y;
            Ks[d + 2][lr] = kv.z; Ks[d + 3][lr] = kv.w;
            float4 vv = *(const float4*)&g_qkv[rowoff + 2 * Dim];
            *(float4*)&Vs[lr][d] = vv;
        }
        __syncthreads();

        float s[4][4] = {};
#pragma unroll 8
        for (int d = 0; d < 64; d++) {
            float4 a4 = *(const float4*)&Qs[d][ty * 4];
            float4 b4 = *(const float4*)&Ks[d][tx * 4];
            float av[4] = {a4.x, a4.y, a4.z, a4.w};
            float bv[4] = {b4.x, b4.y, b4.z, b4.w};
#pragma unroll
            for (int i = 0; i < 4; i++)
#pragma unroll
                for (int j = 0; j < 4; j++)
                    s[i][j] += av[i] * bv[j];
        }

        if (kt == qt) {
#pragma unroll
            for (int i = 0; i < 4; i++)
#pragma unroll
                for (int j = 0; j < 4; j++)
                    s[i][j] = (tx * 4 + j <= ty * 4 + i) ? s[i][j] * 0.125f : -1e30f;
        } else {
#pragma unroll
            for (int i = 0; i < 4; i++)
#pragma unroll
                for (int j = 0; j < 4; j++)
                    s[i][j] *= 0.125f;
        }

#pragma unroll
        for (int i = 0; i < 4; i++) {
            float mt = fmaxf(fmaxf(s[i][0], s[i][1]), fmaxf(s[i][2], s[i][3]));
            mt = redmax16(mt);
            float nm = fmaxf(m[i], mt);
            float corr = __expf(m[i] - nm);
#pragma unroll
            for (int j = 0; j < 4; j++) s[i][j] = __expf(s[i][j] - nm);
            float rs = s[i][0] + s[i][1] + s[i][2] + s[i][3];
            rs = redsum16(rs);
            l[i] = l[i] * corr + rs;
#pragma unroll
            for (int j = 0; j < 4; j++) acc[i][j] *= corr;
            m[i] = nm;
        }

#pragma unroll
        for (int i = 0; i < 4; i++) {
            float4 p4 = make_float4(s[i][0], s[i][1], s[i][2], s[i][3]);
            *(float4*)&Ps[ty * 4 + i][tx * 4] = p4;
        }
        __syncthreads();

#pragma unroll 8
        for (int kc = 0; kc < 64; kc++) {
            float av[4] = {Ps[ty * 4 + 0][kc], Ps[ty * 4 + 1][kc],
                           Ps[ty * 4 + 2][kc], Ps[ty * 4 + 3][kc]};
            float4 b4 = *(const float4*)&Vs[kc][tx * 4];
            float bv[4] = {b4.x, b4.y, b4.z, b4.w};
#pragma unroll
            for (int i = 0; i < 4; i++)
#pragma unroll
                for (int j = 0; j < 4; j++)
                    acc[i][j] += av[i] * bv[j];
        }
        __syncthreads();
    }

#pragma unroll
    for (int i = 0; i < 4; i++) {
        float inv = 1.0f / l[i];
        float4 o = make_float4(acc[i][0] * inv, acc[i][1] * inv,
                               acc[i][2] * inv, acc[i][3] * inv);
        *(float4*)&g_y[(b * Seq + qt * 64 + ty * 4 + i) * Dim + h * HDim + tx * 4] = o;
    }
}

// ===========================================================================
extern "C" void kernel_launch(void* const* d_in, const int* in_sizes, int n_in,
                              void* d_out, int out_size) {
    const float* x    = (const float*)d_in[0];
    const float* fc   = (const float*)d_in[1];
    // d_in[2] = mask — causality is structural, unused
    const float* wqkv = (const float*)d_in[3];
    const float* wo   = (const float*)d_in[4];
    float* out = (float*)d_out;

    float* qkv_ptr = nullptr;
    float* y_ptr   = nullptr;
    cudaGetSymbolAddress((void**)&qkv_ptr, g_qkv);
    cudaGetSymbolAddress((void**)&y_ptr, g_y);

    cudaFuncSetAttribute(attn_kernel, cudaFuncAttributeMaxDynamicSharedMemorySize,
                         ATTN_SMEM_BYTES);

    const int M = Bsz * Seq;  // 4096

    // 1) QKV = X @ Wqkv^T   [4096 x 3072]
    {
        dim3 grid(3 * Dim / 128, M / 128);
        gemm_mma<<<grid, 256>>>(x, wqkv, qkv_ptr, 3 * Dim);
    }
    // 2) RoPE on q, k
    {
        int total = Bsz * Seq * (Dim / 2);
        rope_kernel<<<(total + 255) / 256, 256>>>(fc);
    }
    // 3) attention -> g_y
    {
        dim3 grid(Seq / 64, Bsz * NHead);
        attn_kernel<<<grid, 256, ATTN_SMEM_BYTES>>>();
    }
    // 4) out = Y @ Wo^T   [4096 x 1024]
    {
        dim3 grid(Dim / 128, M / 128);
        gemm_mma<<<grid, 256>>>(y_ptr, wo, out, Dim);
    }
}

// round 4
// speedup vs baseline: 2.3140x; 1.5008x over previous
#include <cuda_runtime.h>
#include <cuda_bf16.h>
#include <cstdint>
#include <math.h>

#define Bsz   2
#define Seq   2048
#define Dim   1024
#define NHead 16
#define HDim  64

__device__ float g_qkv[Bsz * Seq * 3 * Dim];
__device__ float g_y  [Bsz * Seq * Dim];

// ===========================================================================
// mma.sync helpers
// ===========================================================================
__device__ __forceinline__ void ldm_x4(uint32_t* r, uint32_t addr) {
    asm volatile("ldmatrix.sync.aligned.m8n8.x4.shared.b16 {%0,%1,%2,%3}, [%4];"
                 : "=r"(r[0]), "=r"(r[1]), "=r"(r[2]), "=r"(r[3]) : "r"(addr));
}
__device__ __forceinline__ void mma_bf16(float* d, const uint32_t* a,
                                         const uint32_t* b) {
    asm volatile(
        "mma.sync.aligned.m16n8k16.row.col.f32.bf16.bf16.f32 "
        "{%0,%1,%2,%3}, {%4,%5,%6,%7}, {%8,%9}, {%0,%1,%2,%3};"
        : "+f"(d[0]), "+f"(d[1]), "+f"(d[2]), "+f"(d[3])
        : "r"(a[0]), "r"(a[1]), "r"(a[2]), "r"(a[3]), "r"(b[0]), "r"(b[1]));
}
__device__ __forceinline__ uint32_t smem_u32(const void* p) {
    uint32_t a;
    asm("{ .reg .u64 t; cvta.to.shared.u64 t, %1; cvt.u32.u64 %0, t; }"
        : "=r"(a) : "l"(p));
    return a;
}
__device__ __forceinline__ uint32_t pk_bf2(__nv_bfloat16 a, __nv_bfloat16 b) {
    __nv_bfloat162 t(a, b);
    return *reinterpret_cast<uint32_t*>(&t);
}
__device__ __forceinline__ void cvt_split4(float4 v, uint2* hi, uint2* lo) {
    __nv_bfloat16 hx = __float2bfloat16(v.x), hy = __float2bfloat16(v.y);
    __nv_bfloat16 hz = __float2bfloat16(v.z), hw = __float2bfloat16(v.w);
    *hi = make_uint2(pk_bf2(hx, hy), pk_bf2(hz, hw));
    *lo = make_uint2(
        pk_bf2(__float2bfloat16(v.x - __bfloat162float(hx)),
               __float2bfloat16(v.y - __bfloat162float(hy))),
        pk_bf2(__float2bfloat16(v.z - __bfloat162float(hz)),
               __float2bfloat16(v.w - __bfloat162float(hw))));
}

// ===========================================================================
// HMMA GEMM (unchanged from R3): C = A[M][1024] @ B[N][1024]^T
// ===========================================================================
#define GK   1024
#define BK   32
#define LDSS 40

__global__ __launch_bounds__(256) void gemm_mma(const float* __restrict__ A,
                                                const float* __restrict__ Bm,
                                                float* __restrict__ C, int N) {
    __shared__ __align__(16) __nv_bfloat16 sAh[128 * LDSS];
    __shared__ __align__(16) __nv_bfloat16 sAl[128 * LDSS];
    __shared__ __align__(16) __nv_bfloat16 sBh[128 * LDSS];
    __shared__ __align__(16) __nv_bfloat16 sBl[128 * LDSS];

    const int t = threadIdx.x;
    const int lane = t & 31, wid = t >> 5;
    const int wm = (wid & 1) * 64;
    const int wn = (wid >> 1) * 32;
    const int bm = blockIdx.y * 128, bn = blockIdx.x * 128;

    const uint32_t uAh = smem_u32(sAh), uAl = smem_u32(sAl);
    const uint32_t uBh = smem_u32(sBh), uBl = smem_u32(sBl);

    const int r0 = t >> 2, c0 = (t & 3) * 4;

    float4 ra[4], rb[4];
    float d[4][4][4];
#pragma unroll
    for (int mi = 0; mi < 4; mi++)
#pragma unroll
        for (int nj = 0; nj < 4; nj++)
#pragma unroll
            for (int e = 0; e < 4; e++) d[mi][nj][e] = 0.f;

#pragma unroll
    for (int p = 0; p < 4; p++) {
        int row = r0 + (p >> 1) * 64, col = c0 + (p & 1) * 16;
        ra[p] = *(const float4*)(A + (size_t)(bm + row) * GK + col);
        rb[p] = *(const float4*)(Bm + (size_t)(bn + row) * GK + col);
    }

    for (int it = 0; it < GK / BK; it++) {
#pragma unroll
        for (int p = 0; p < 4; p++) {
            int row = r0 + (p >> 1) * 64, col = c0 + (p & 1) * 16;
            int off = row * LDSS + col;
            cvt_split4(ra[p], (uint2*)&sAh[off], (uint2*)&sAl[off]);
            cvt_split4(rb[p], (uint2*)&sBh[off], (uint2*)&sBl[off]);
        }
        __syncthreads();

        if (it + 1 < GK / BK) {
            const int k0 = (it + 1) * BK;
#pragma unroll
            for (int p = 0; p < 4; p++) {
                int row = r0 + (p >> 1) * 64, col = c0 + (p & 1) * 16;
                ra[p] = *(const float4*)(A + (size_t)(bm + row) * GK + k0 + col);
                rb[p] = *(const float4*)(Bm + (size_t)(bn + row) * GK + k0 + col);
            }
        }

#pragma unroll
        for (int ks = 0; ks < 2; ks++) {
            const int k0 = ks * 16;
            uint32_t ah[4][4], al[4][4];
            const int arow = wm + (lane & 15);
            const int acol = k0 + (lane >> 4) * 8;
#pragma unroll
            for (int mi = 0; mi < 4; mi++) {
                uint32_t o = (uint32_t)(((arow + mi * 16) * LDSS + acol) * 2);
                ldm_x4(ah[mi], uAh + o);
                ldm_x4(al[mi], uAl + o);
            }
            uint32_t bh[2][4], bl[2][4];
            const int brow = wn + (lane & 7) + ((lane & 16) >> 1);
            const int bcol = k0 + ((lane & 8) ? 8 : 0);
#pragma unroll
            for (int nb = 0; nb < 2; nb++) {
                uint32_t o = (uint32_t)(((brow + nb * 16) * LDSS + bcol) * 2);
                ldm_x4(bh[nb], uBh + o);
                ldm_x4(bl[nb], uBl + o);
            }
#pragma unroll
            for (int mi = 0; mi < 4; mi++)
#pragma unroll
                for (int nj = 0; nj < 4; nj++) {
                    const uint32_t* fh = &bh[nj >> 1][(nj & 1) * 2];
                    const uint32_t* fl = &bl[nj >> 1][(nj & 1) * 2];
                    mma_bf16(d[mi][nj], ah[mi], fh);
                    mma_bf16(d[mi][nj], ah[mi], fl);
                    mma_bf16(d[mi][nj], al[mi], fh);
                }
        }
        __syncthreads();
    }

#pragma unroll
    for (int mi = 0; mi < 4; mi++)
#pragma unroll
        for (int nj = 0; nj < 4; nj++) {
            int row = bm + wm + mi * 16 + (lane >> 2);
            int col = bn + wn + nj * 8 + (lane & 3) * 2;
            *(float2*)&C[(size_t)row * N + col] =
                make_float2(d[mi][nj][0], d[mi][nj][1]);
            *(float2*)&C[(size_t)(row + 8) * N + col] =
                make_float2(d[mi][nj][2], d[mi][nj][3]);
        }
}

// ===========================================================================
// RoPE (unchanged)
// ===========================================================================
__global__ __launch_bounds__(256) void rope_kernel(const float* __restrict__ fc) {
    int idx = blockIdx.x * blockDim.x + threadIdx.x;
    const int total = Bsz * Seq * (Dim / 2);
    if (idx >= total) return;
    int p = idx % (Dim / 2);
    int s = (idx / (Dim / 2)) % Seq;
    int b = idx / (Seq * (Dim / 2));
    int j = p & 31;
    float c  = fc[s * 64 + j * 2 + 0];
    float sn = fc[s * 64 + j * 2 + 1];
    int base = (b * Seq + s) * 3 * Dim;
    int off  = p * 2;

    float* q = &g_qkv[base + off];
    float xr = q[0], xi = q[1];
    q[0] = xr * c - xi * sn;
    q[1] = xi * c + xr * sn;

    float* kk = &g_qkv[base + Dim + off];
    xr = kk[0]; xi = kk[1];
    kk[0] = xr * c - xi * sn;
    kk[1] = xi * c + xr * sn;
}

// ===========================================================================
// HMMA flash attention. CTA: 128 q-rows x (b,h). 8 warps, warp = 16 q-rows.
// K-tile 128. bf16 3-term for S and PV, fp32 accum, online softmax.
// ===========================================================================
#define LDK 72    // bf16 row stride for K/Q tiles [row][d]
#define LDV 136   // bf16 row stride for transposed V [d][kv]
#define SZ_K  (128 * LDK * 2)          // 18432 B per term
#define OFF_KH 0
#define OFF_KL SZ_K
#define OFF_VH (2 * SZ_K)
#define OFF_VL (2 * SZ_K + 64 * LDV * 2)
#define ATTN_SMEM (2 * SZ_K + 2 * 64 * LDV * 2)   // 71680 B

__global__ __launch_bounds__(256, 1) void attn_mma() {
    extern __shared__ char smc[];
    __nv_bfloat16* sKh = (__nv_bfloat16*)(smc + OFF_KH);
    __nv_bfloat16* sKl = (__nv_bfloat16*)(smc + OFF_KL);
    __nv_bfloat16* sVh = (__nv_bfloat16*)(smc + OFF_VH);
    __nv_bfloat16* sVl = (__nv_bfloat16*)(smc + OFF_VL);
    const uint32_t uKh = smem_u32(sKh), uKl = smem_u32(sKl);
    const uint32_t uVh = smem_u32(sVh), uVl = smem_u32(sVl);

    const int tid = threadIdx.x, lane = tid & 31, w = tid >> 5;
    const int qt = blockIdx.x, bh = blockIdx.y;
    const int b = bh >> 4, h = bh & 15;
    const int q0w = w * 16;

    // ldmatrix lane->row/col selectors
    const int la_r = (lane & 7) + ((lane & 8) ? 8 : 0);   // A-pattern row
    const int la_c = (lane & 16) ? 8 : 0;                 // A-pattern col
    const int lb_r = (lane & 7) + ((lane & 16) ? 8 : 0);  // B-pattern row
    const int lb_c = (lane & 8) ? 8 : 0;                  // B-pattern col

    // fill mapping: thread -> row tid>>1, d-half (tid&1)*32
    const int frow = tid >> 1, fdh = (tid & 1) * 32;

    // ---- stage Q (x0.125) into K region, ldmatrix to regs ----
    {
        size_t gq = (size_t)(b * Seq + qt * 128 + frow) * 3 * Dim + h * HDim + fdh;
#pragma unroll
        for (int j = 0; j < 8; j++) {
            float4 v = *(const float4*)&g_qkv[gq + j * 4];
            v.x *= 0.125f; v.y *= 0.125f; v.z *= 0.125f; v.w *= 0.125f;
            int off = frow * LDK + fdh + j * 4;
            cvt_split4(v, (uint2*)&sKh[off], (uint2*)&sKl[off]);
        }
    }
    __syncthreads();
    uint32_t qhf[4][4], qlf[4][4];
#pragma unroll
    for (int ks = 0; ks < 4; ks++) {
        uint32_t o = (uint32_t)(((q0w + la_r) * LDK + ks * 16 + la_c) * 2);
        ldm_x4(qhf[ks], uKh + o);
        ldm_x4(qlf[ks], uKl + o);
    }
    __syncthreads();

    float accO[8][4];
#pragma unroll
    for (int i = 0; i < 8; i++)
#pragma unroll
        for (int e = 0; e < 4; e++) accO[i][e] = 0.f;
    float m0 = -1e30f, m1 = -1e30f, l0 = 0.f, l1 = 0.f;

    for (int kt = 0; kt <= qt; kt++) {
        // ---- fill K (row-major) and V (transposed), bf16 hi/lo ----
        {
            size_t gr = (size_t)(b * Seq + kt * 128 + frow) * 3 * Dim + h * HDim + fdh;
#pragma unroll
            for (int j = 0; j < 8; j++) {
                float4 kv4 = *(const float4*)&g_qkv[gr + Dim + j * 4];
                int off = frow * LDK + fdh + j * 4;
                cvt_split4(kv4, (uint2*)&sKh[off], (uint2*)&sKl[off]);
                float4 vv4 = *(const float4*)&g_qkv[gr + 2 * Dim + j * 4];
                float vv[4] = {vv4.x, vv4.y, vv4.z, vv4.w};
#pragma unroll
                for (int e = 0; e < 4; e++) {
                    int dd = fdh + j * 4 + e;
                    __nv_bfloat16 hi = __float2bfloat16(vv[e]);
                    sVh[dd * LDV + frow] = hi;
                    sVl[dd * LDV + frow] =
                        __float2bfloat16(vv[e] - __bfloat162float(hi));
                }
            }
        }
        __syncthreads();

        // ---- S = Q K^T (3-term) ----
        float sa[16][4];
#pragma unroll
        for (int i = 0; i < 16; i++)
#pragma unroll
            for (int e = 0; e < 4; e++) sa[i][e] = 0.f;

#pragma unroll
        for (int ks = 0; ks < 4; ks++) {
#pragma unroll
            for (int bg = 0; bg < 8; bg++) {
                uint32_t kh[4], kl[4];
                uint32_t o = (uint32_t)(((bg * 16 + lb_r) * LDK + ks * 16 + lb_c) * 2);
                ldm_x4(kh, uKh + o);
                ldm_x4(kl, uKl + o);
                mma_bf16(sa[2 * bg],     qhf[ks], kh);
                mma_bf16(sa[2 * bg],     qhf[ks], kl);
                mma_bf16(sa[2 * bg],     qlf[ks], kh);
                mma_bf16(sa[2 * bg + 1], qhf[ks], kh + 2);
                mma_bf16(sa[2 * bg + 1], qhf[ks], kl + 2);
                mma_bf16(sa[2 * bg + 1], qlf[ks], kh + 2);
            }
        }

        // ---- causal mask (diagonal tile) ----
        const int r0 = q0w + (lane >> 2), r1 = r0 + 8;
        if (kt == qt) {
#pragma unroll
            for (int nt = 0; nt < 16; nt++) {
                int c = nt * 8 + (lane & 3) * 2;
                if (c > r0)     sa[nt][0] = -1e30f;
                if (c + 1 > r0) sa[nt][1] = -1e30f;
                if (c > r1)     sa[nt][2] = -1e30f;
                if (c + 1 > r1) sa[nt][3] = -1e30f;
            }
        }

        // ---- online softmax ----
        float mx0 = -1e30f, mx1 = -1e30f;
#pragma unroll
        for (int nt = 0; nt < 16; nt++) {
            mx0 = fmaxf(mx0, fmaxf(sa[nt][0], sa[nt][1]));
            mx1 = fmaxf(mx1, fmaxf(sa[nt][2], sa[nt][3]));
        }
        mx0 = fmaxf(mx0, __shfl_xor_sync(0xffffffffu, mx0, 1));
        mx0 = fmaxf(mx0, __shfl_xor_sync(0xffffffffu, mx0, 2));
        mx1 = fmaxf(mx1, __shfl_xor_sync(0xffffffffu, mx1, 1));
        mx1 = fmaxf(mx1, __shfl_xor_sync(0xffffffffu, mx1, 2));

        float nm0 = fmaxf(m0, mx0), nm1 = fmaxf(m1, mx1);
        float c0 = __expf(m0 - nm0), c1 = __expf(m1 - nm1);
        m0 = nm0; m1 = nm1;

        float rs0 = 0.f, rs1 = 0.f;
#pragma unroll
        for (int nt = 0; nt < 16; nt++) {
            sa[nt][0] = __expf(sa[nt][0] - m0);
            sa[nt][1] = __expf(sa[nt][1] - m0);
            sa[nt][2] = __expf(sa[nt][2] - m1);
            sa[nt][3] = __expf(sa[nt][3] - m1);
            rs0 += sa[nt][0] + sa[nt][1];
            rs1 += sa[nt][2] + sa[nt][3];
        }
        rs0 += __shfl_xor_sync(0xffffffffu, rs0, 1);
        rs0 += __shfl_xor_sync(0xffffffffu, rs0, 2);
        rs1 += __shfl_xor_sync(0xffffffffu, rs1, 1);
        rs1 += __shfl_xor_sync(0xffffffffu, rs1, 2);
        l0 = l0 * c0 + rs0;
        l1 = l1 * c1 + rs1;
#pragma unroll
        for (int dt = 0; dt < 8; dt++) {
            accO[dt][0] *= c0; accO[dt][1] *= c0;
            accO[dt][2] *= c1; accO[dt][3] *= c1;
        }

        // ---- O += P V (3-term) ----
#pragma unroll
        for (int ks = 0; ks < 8; ks++) {
            uint32_t ph[4], pl[4];
#pragma unroll
            for (int half = 0; half < 2; half++) {
                const float* s4 = sa[2 * ks + half];
                __nv_bfloat16 h0 = __float2bfloat16(s4[0]);
                __nv_bfloat16 h1 = __float2bfloat16(s4[1]);
                __nv_bfloat16 h2 = __float2bfloat16(s4[2]);
                __nv_bfloat16 h3 = __float2bfloat16(s4[3]);
                ph[2 * half + 0] = pk_bf2(h0, h1);
                ph[2 * half + 1] = pk_bf2(h2, h3);
                pl[2 * half + 0] = pk_bf2(
                    __float2bfloat16(s4[0] - __bfloat162float(h0)),
                    __float2bfloat16(s4[1] - __bfloat162float(h1)));
                pl[2 * half + 1] = pk_bf2(
                    __float2bfloat16(s4[2] - __bfloat162float(h2)),
                    __float2bfloat16(s4[3] - __bfloat162float(h3)));
            }
            // reorder: a-frag = [t0c0pair, t0rows+8, t1c0pair, t1rows+8]
            uint32_t pa_h[4] = {ph[0], ph[1], ph[2], ph[3]};
            uint32_t pa_l[4] = {pl[0], pl[1], pl[2], pl[3]};
#pragma unroll
            for (int vg = 0; vg < 4; vg++) {
                uint32_t vh[4], vl[4];
                uint32_t o = (uint32_t)(((vg * 16 + lb_r) * LDV + ks * 16 + lb_c) * 2);
                ldm_x4(vh, uVh + o);
                ldm_x4(vl, uVl + o);
                mma_bf16(accO[2 * vg],     pa_h, vh);
                mma_bf16(accO[2 * vg],     pa_h, vl);
                mma_bf16(accO[2 * vg],     pa_l, vh);
                mma_bf16(accO[2 * vg + 1], pa_h, vh + 2);
                mma_bf16(accO[2 * vg + 1], pa_h, vl + 2);
                mma_bf16(accO[2 * vg + 1], pa_l, vh + 2);
            }
        }
        __syncthreads();
    }

    // ---- write O / l ----
    const float il0 = 1.f / l0, il1 = 1.f / l1;
    const int row0 = qt * 128 + q0w + (lane >> 2);
    const int row1 = row0 + 8;
#pragma unroll
    for (int dt = 0; dt < 8; dt++) {
        int col = h * HDim + dt * 8 + (lane & 3) * 2;
        *(float2*)&g_y[(size_t)(b * Seq + row0) * Dim + col] =
            make_float2(accO[dt][0] * il0, accO[dt][1] * il0);
        *(float2*)&g_y[(size_t)(b * Seq + row1) * Dim + col] =
            make_float2(accO[dt][2] * il1, accO[dt][3] * il1);
    }
}

// ===========================================================================
extern "C" void kernel_launch(void* const* d_in, const int* in_sizes, int n_in,
                              void* d_out, int out_size) {
    const float* x    = (const float*)d_in[0];
    const float* fc   = (const float*)d_in[1];
    // d_in[2] = mask — causality structural, unused
    const float* wqkv = (const float*)d_in[3];
    const float* wo   = (const float*)d_in[4];
    float* out = (float*)d_out;

    float* qkv_ptr = nullptr;
    float* y_ptr   = nullptr;
    cudaGetSymbolAddress((void**)&qkv_ptr, g_qkv);
    cudaGetSymbolAddress((void**)&y_ptr, g_y);

    cudaFuncSetAttribute(attn_mma, cudaFuncAttributeMaxDynamicSharedMemorySize,
                         ATTN_SMEM);

    const int M = Bsz * Seq;

    {
        dim3 grid(3 * Dim / 128, M / 128);
        gemm_mma<<<grid, 256>>>(x, wqkv, qkv_ptr, 3 * Dim);
    }
    {
        int total = Bsz * Seq * (Dim / 2);
        rope_kernel<<<(total + 255) / 256, 256>>>(fc);
    }
    {
        dim3 grid(Seq / 128, Bsz * NHead);
        attn_mma<<<grid, 256, ATTN_SMEM>>>();
    }
    {
        dim3 grid(Dim / 128, M / 128);
        gemm_mma<<<grid, 256>>>(y_ptr, wo, out, Dim);
    }
}

// round 5
// speedup vs baseline: 2.7146x; 1.1731x over previous
#include <cuda_runtime.h>
#include <cuda_bf16.h>
#include <cstdint>
#include <math.h>

#define Bsz   2
#define Seq   2048
#define Dim   1024
#define NHead 16
#define HDim  64

// fp32 QKV scratch
__device__ float g_qkv[Bsz * Seq * 3 * Dim];
// pre-split bf16 operands
__device__ __nv_bfloat16 g_Xh[4096 * 1024],  g_Xl[4096 * 1024];
__device__ __nv_bfloat16 g_Wqh[3072 * 1024], g_Wql[3072 * 1024];
__device__ __nv_bfloat16 g_Woh[1024 * 1024], g_Wol[1024 * 1024];
// per-(b,h) planes [32][2048][64]
__device__ __nv_bfloat16 g_Qh[32 * 2048 * 64], g_Ql[32 * 2048 * 64];
__device__ __nv_bfloat16 g_Kh[32 * 2048 * 64], g_Kl[32 * 2048 * 64];
__device__ __nv_bfloat16 g_Vh[32 * 2048 * 64], g_Vl[32 * 2048 * 64];
// attention output, pre-split
__device__ __nv_bfloat16 g_Yh[4096 * 1024], g_Yl[4096 * 1024];

// ===========================================================================
// helpers
// ===========================================================================
__device__ __forceinline__ void ldm_x4(uint32_t* r, uint32_t addr) {
    asm volatile("ldmatrix.sync.aligned.m8n8.x4.shared.b16 {%0,%1,%2,%3}, [%4];"
                 : "=r"(r[0]), "=r"(r[1]), "=r"(r[2]), "=r"(r[3]) : "r"(addr));
}
__device__ __forceinline__ void ldm_x4_t(uint32_t* r, uint32_t addr) {
    asm volatile("ldmatrix.sync.aligned.m8n8.x4.trans.shared.b16 {%0,%1,%2,%3}, [%4];"
                 : "=r"(r[0]), "=r"(r[1]), "=r"(r[2]), "=r"(r[3]) : "r"(addr));
}
__device__ __forceinline__ void mma_bf16(float* d, const uint32_t* a,
                                         const uint32_t* b) {
    asm volatile(
        "mma.sync.aligned.m16n8k16.row.col.f32.bf16.bf16.f32 "
        "{%0,%1,%2,%3}, {%4,%5,%6,%7}, {%8,%9}, {%0,%1,%2,%3};"
        : "+f"(d[0]), "+f"(d[1]), "+f"(d[2]), "+f"(d[3])
        : "r"(a[0]), "r"(a[1]), "r"(a[2]), "r"(a[3]), "r"(b[0]), "r"(b[1]));
}
__device__ __forceinline__ uint32_t smem_u32(const void* p) {
    uint32_t a;
    asm("{ .reg .u64 t; cvta.to.shared.u64 t, %1; cvt.u32.u64 %0, t; }"
        : "=r"(a) : "l"(p));
    return a;
}
__device__ __forceinline__ uint32_t pk_bf2(__nv_bfloat16 a, __nv_bfloat16 b) {
    __nv_bfloat162 t(a, b);
    return *reinterpret_cast<uint32_t*>(&t);
}
__device__ __forceinline__ void cvt_split4(float4 v, uint2* hi, uint2* lo) {
    __nv_bfloat16 hx = __float2bfloat16(v.x), hy = __float2bfloat16(v.y);
    __nv_bfloat16 hz = __float2bfloat16(v.z), hw = __float2bfloat16(v.w);
    *hi = make_uint2(pk_bf2(hx, hy), pk_bf2(hz, hw));
    *lo = make_uint2(
        pk_bf2(__float2bfloat16(v.x - __bfloat162float(hx)),
               __float2bfloat16(v.y - __bfloat162float(hy))),
        pk_bf2(__float2bfloat16(v.z - __bfloat162float(hz)),
               __float2bfloat16(v.w - __bfloat162float(hw))));
}
__device__ __forceinline__ void cpa16(uint32_t s, const void* g) {
    asm volatile("cp.async.cg.shared.global [%0], [%1], 16;" :: "r"(s), "l"(g));
}
#define CP_COMMIT() asm volatile("cp.async.commit_group;")
#define CP_WAIT1()  asm volatile("cp.async.wait_group 1;")
#define CP_WAIT0()  asm volatile("cp.async.wait_group 0;")

// ===========================================================================
// split: fp32 -> bf16 hi/lo (vectorized by 4)
// ===========================================================================
__global__ __launch_bounds__(256) void split_kernel(const float* __restrict__ src,
                                                    __nv_bfloat16* __restrict__ hi,
                                                    __nv_bfloat16* __restrict__ lo,
                                                    int n4) {
    int i = blockIdx.x * blockDim.x + threadIdx.x;
    if (i >= n4) return;
    float4 v = ((const float4*)src)[i];
    uint2 h, l;
    cvt_split4(v, &h, &l);
    ((uint2*)hi)[i] = h;
    ((uint2*)lo)[i] = l;
}

// ===========================================================================
// rope + split to per-(b,h) planes. thread = (b, s, p), p in [0,512)
// ===========================================================================
__device__ __forceinline__ void store_split2(__nv_bfloat16* hi, __nv_bfloat16* lo,
                                             size_t o, float a, float b2) {
    __nv_bfloat16 ha = __float2bfloat16(a), hb = __float2bfloat16(b2);
    *(__nv_bfloat162*)(hi + o) = __nv_bfloat162(ha, hb);
    *(__nv_bfloat162*)(lo + o) = __nv_bfloat162(
        __float2bfloat16(a - __bfloat162float(ha)),
        __float2bfloat16(b2 - __bfloat162float(hb)));
}

__global__ __launch_bounds__(256) void rope_split(const float* __restrict__ fc) {
    int idx = blockIdx.x * blockDim.x + threadIdx.x;
    if (idx >= Bsz * Seq * 512) return;
    int p = idx & 511;
    int s = (idx >> 9) & 2047;
    int b = idx >> 20;
    int h = p >> 5, j = p & 31;
    float c  = fc[s * 64 + j * 2 + 0];
    float sn = fc[s * 64 + j * 2 + 1];
    const float* src = g_qkv + (size_t)(b * Seq + s) * 3 * Dim;
    int d2 = p * 2;

    float qr = src[d2], qi = src[d2 + 1];
    float oqr = (qr * c - qi * sn) * 0.125f;
    float oqi = (qi * c + qr * sn) * 0.125f;
    float kr = src[Dim + d2], ki = src[Dim + d2 + 1];
    float okr = kr * c - ki * sn;
    float oki = ki * c + kr * sn;
    float v0 = src[2 * Dim + d2], v1 = src[2 * Dim + d2 + 1];

    size_t o = ((size_t)(b * NHead + h) * Seq + s) * HDim + 2 * j;
    store_split2(g_Qh, g_Ql, o, oqr, oqi);
    store_split2(g_Kh, g_Kl, o, okr, oki);
    store_split2(g_Vh, g_Vl, o, v0, v1);
}

// ===========================================================================
// gemm_bf: C[M][N] = A[M][1024] @ B[N][1024]^T, A/B pre-split bf16 hi/lo.
// 128x128 tile, BK=32, 256 threads, cp.async 2-stage pipeline, 3-term HMMA.
// ===========================================================================
#define LDSS 40
#define G_ARR (128 * LDSS * 2)       // 10240 B
#define G_STAGE (4 * G_ARR)          // 40960 B
#define GEMM_SMEM (2 * G_STAGE)      // 81920 B
#define GOA_H 0
#define GOA_L G_ARR
#define GOB_H (2 * G_ARR)
#define GOB_L (3 * G_ARR)
#define G_NIT 32

__device__ __forceinline__ void gemm_issue(
    int it, uint32_t sb, int bm, int bn, int row, int cp0,
    const __nv_bfloat16* Ah, const __nv_bfloat16* Al,
    const __nv_bfloat16* Bh, const __nv_bfloat16* Bl) {
    if (it < G_NIT) {
        uint32_t st = sb + (it & 1) * G_STAGE;
        int k0 = it * 32;
        size_t ga = (size_t)(bm + row) * 1024 + k0 + cp0 * 8;
        size_t gb = (size_t)(bn + row) * 1024 + k0 + cp0 * 8;
        uint32_t so = row * (LDSS * 2) + cp0 * 16;
        cpa16(st + GOA_H + so,      Ah + ga);
        cpa16(st + GOA_H + so + 16, Ah + ga + 8);
        cpa16(st + GOA_L + so,      Al + ga);
        cpa16(st + GOA_L + so + 16, Al + ga + 8);
        cpa16(st + GOB_H + so,      Bh + gb);
        cpa16(st + GOB_H + so + 16, Bh + gb + 8);
        cpa16(st + GOB_L + so,      Bl + gb);
        cpa16(st + GOB_L + so + 16, Bl + gb + 8);
    }
    CP_COMMIT();
}

__global__ __launch_bounds__(256) void gemm_bf(
    const __nv_bfloat16* __restrict__ Ah, const __nv_bfloat16* __restrict__ Al,
    const __nv_bfloat16* __restrict__ Bh, const __nv_bfloat16* __restrict__ Bl,
    float* __restrict__ C, int N) {
    extern __shared__ char smem[];
    const uint32_t sb = smem_u32(smem);
    const int t = threadIdx.x, lane = t & 31, wid = t >> 5;
    const int wm = (wid & 1) * 64, wn = (wid >> 1) * 32;
    const int bm = blockIdx.y * 128, bn = blockIdx.x * 128;
    const int row = t >> 1, cp0 = (t & 1) * 2;

    float d[4][4][4];
#pragma unroll
    for (int mi = 0; mi < 4; mi++)
#pragma unroll
        for (int nj = 0; nj < 4; nj++)
#pragma unroll
            for (int e = 0; e < 4; e++) d[mi][nj][e] = 0.f;

    gemm_issue(0, sb, bm, bn, row, cp0, Ah, Al, Bh, Bl);
    gemm_issue(1, sb, bm, bn, row, cp0, Ah, Al, Bh, Bl);

    for (int it = 0; it < G_NIT; it++) {
        CP_WAIT1();
        __syncthreads();
        const uint32_t st = sb + (it & 1) * G_STAGE;
#pragma unroll
        for (int ks = 0; ks < 2; ks++) {
            const int k0 = ks * 16;
            uint32_t ah[4][4], al[4][4];
            const int arow = wm + (lane & 15);
            const int acol = k0 + ((lane & 16) ? 8 : 0);
#pragma unroll
            for (int mi = 0; mi < 4; mi++) {
                uint32_t o = (uint32_t)(((arow + mi * 16) * LDSS + acol) * 2);
                ldm_x4(ah[mi], st + GOA_H + o);
                ldm_x4(al[mi], st + GOA_L + o);
            }
            uint32_t bh[2][4], bl[2][4];
            const int brow = wn + (lane & 7) + ((lane & 16) >> 1);
            const int bcol = k0 + ((lane & 8) ? 8 : 0);
#pragma unroll
            for (int nb = 0; nb < 2; nb++) {
                uint32_t o = (uint32_t)(((brow + nb * 16) * LDSS + bcol) * 2);
                ldm_x4(bh[nb], st + GOB_H + o);
                ldm_x4(bl[nb], st + GOB_L + o);
            }
#pragma unroll
            for (int mi = 0; mi < 4; mi++)
#pragma unroll
                for (int nj = 0; nj < 4; nj++) {
                    const uint32_t* fh = &bh[nj >> 1][(nj & 1) * 2];
                    const uint32_t* fl = &bl[nj >> 1][(nj & 1) * 2];
                    mma_bf16(d[mi][nj], ah[mi], fh);
                    mma_bf16(d[mi][nj], ah[mi], fl);
                    mma_bf16(d[mi][nj], al[mi], fh);
                }
        }
        __syncthreads();
        gemm_issue(it + 2, sb, bm, bn, row, cp0, Ah, Al, Bh, Bl);
    }

#pragma unroll
    for (int mi = 0; mi < 4; mi++)
#pragma unroll
        for (int nj = 0; nj < 4; nj++) {
            int r = bm + wm + mi * 16 + (lane >> 2);
            int c = bn + wn + nj * 8 + (lane & 3) * 2;
            *(float2*)&C[(size_t)r * N + c] =
                make_float2(d[mi][nj][0], d[mi][nj][1]);
            *(float2*)&C[(size_t)(r + 8) * N + c] =
                make_float2(d[mi][nj][2], d[mi][nj][3]);
        }
}

// ===========================================================================
// attention: 128 q-rows x (b,h); k-tile 128; cp.async double-buffered K/V;
// V row-major with ldmatrix.trans; 3-term HMMA; online softmax.
// ===========================================================================
#define LDKV 72
#define A_ARR (128 * LDKV * 2)       // 18432 B
#define A_STAGE (4 * A_ARR)          // 73728 B
#define ATTN_SMEM (2 * A_STAGE)      // 147456 B
#define AKH 0
#define AKL A_ARR
#define AVH (2 * A_ARR)
#define AVL (3 * A_ARR)

__device__ __forceinline__ void attn_issue(int kt, int qt, uint32_t sb,
                                           size_t base, int row, int j0) {
    if (kt <= qt) {
        uint32_t st = sb + (kt & 1) * A_STAGE;
        size_t g = base + (size_t)(kt * 128 + row) * 64 + j0 * 8;
        uint32_t so = row * (LDKV * 2) + j0 * 16;
        for (int c = 0; c < 4; c++) {
            cpa16(st + AKH + so + c * 16, g_Kh + g + c * 8);
            cpa16(st + AKL + so + c * 16, g_Kl + g + c * 8);
            cpa16(st + AVH + so + c * 16, g_Vh + g + c * 8);
            cpa16(st + AVL + so + c * 16, g_Vl + g + c * 8);
        }
    }
    CP_COMMIT();
}

__global__ __launch_bounds__(256, 1) void attn_bf() {
    extern __shared__ char smc[];
    const uint32_t sb = smem_u32(smc);
    const int tid = threadIdx.x, lane = tid & 31, w = tid >> 5;
    const int qt = blockIdx.x, bh = blockIdx.y;
    const int b = bh >> 4, h = bh & 15;
    const size_t base = (size_t)bh * Seq * HDim;
    const int q0w = w * 16;
    const int row = tid >> 1, j0 = (tid & 1) * 4;

    const int la_r = lane & 15;                            // A-pattern
    const int la_c = (lane & 16) ? 8 : 0;
    const int lb_r = (lane & 7) + ((lane & 16) >> 1);      // B-pattern (non-trans)
    const int lb_c = (lane & 8) ? 8 : 0;
    const int lv_r = lane & 15;                            // B-pattern (trans V)
    const int lv_c = (lane & 16) ? 8 : 0;

    // ---- stage Q into buf0 K region, extract frags ----
    {
        size_t gq = base + (size_t)(qt * 128 + row) * 64 + j0 * 8;
        uint32_t so = row * (LDKV * 2) + j0 * 16;
        for (int c = 0; c < 4; c++) {
            cpa16(sb + AKH + so + c * 16, g_Qh + gq + c * 8);
            cpa16(sb + AKL + so + c * 16, g_Ql + gq + c * 8);
        }
    }
    CP_COMMIT();
    CP_WAIT0();
    __syncthreads();
    uint32_t qhf[4][4], qlf[4][4];
#pragma unroll
    for (int ks = 0; ks < 4; ks++) {
        uint32_t o = (uint32_t)(((q0w + la_r) * LDKV + ks * 16 + la_c) * 2);
        ldm_x4(qhf[ks], sb + AKH + o);
        ldm_x4(qlf[ks], sb + AKL + o);
    }
    __syncthreads();

    float accO[8][4];
#pragma unroll
    for (int i = 0; i < 8; i++)
#pragma unroll
        for (int e = 0; e < 4; e++) accO[i][e] = 0.f;
    float m0 = -1e30f, m1 = -1e30f, l0 = 0.f, l1 = 0.f;

    attn_issue(0, qt, sb, base, row, j0);
    attn_issue(1, qt, sb, base, row, j0);

    for (int kt = 0; kt <= qt; kt++) {
        CP_WAIT1();
        __syncthreads();
        const uint32_t st = sb + (kt & 1) * A_STAGE;

        // ---- S = Q K^T (3-term) ----
        float sa[16][4];
#pragma unroll
        for (int i = 0; i < 16; i++)
#pragma unroll
            for (int e = 0; e < 4; e++) sa[i][e] = 0.f;

#pragma unroll
        for (int ks = 0; ks < 4; ks++) {
#pragma unroll
            for (int bg = 0; bg < 8; bg++) {
                uint32_t kh[4], kl[4];
                uint32_t o = (uint32_t)(((bg * 16 + lb_r) * LDKV + ks * 16 + lb_c) * 2);
                ldm_x4(kh, st + AKH + o);
                ldm_x4(kl, st + AKL + o);
                mma_bf16(sa[2 * bg],     qhf[ks], kh);
                mma_bf16(sa[2 * bg],     qhf[ks], kl);
                mma_bf16(sa[2 * bg],     qlf[ks], kh);
                mma_bf16(sa[2 * bg + 1], qhf[ks], kh + 2);
                mma_bf16(sa[2 * bg + 1], qhf[ks], kl + 2);
                mma_bf16(sa[2 * bg + 1], qlf[ks], kh + 2);
            }
        }

        // ---- causal mask on diagonal tile ----
        const int r0 = q0w + (lane >> 2), r1 = r0 + 8;
        if (kt == qt) {
#pragma unroll
            for (int nt = 0; nt < 16; nt++) {
                int c = nt * 8 + (lane & 3) * 2;
                if (c > r0)     sa[nt][0] = -1e30f;
                if (c + 1 > r0) sa[nt][1] = -1e30f;
                if (c > r1)     sa[nt][2] = -1e30f;
                if (c + 1 > r1) sa[nt][3] = -1e30f;
            }
        }

        // ---- online softmax ----
        float mx0 = -1e30f, mx1 = -1e30f;
#pragma unroll
        for (int nt = 0; nt < 16; nt++) {
            mx0 = fmaxf(mx0, fmaxf(sa[nt][0], sa[nt][1]));
            mx1 = fmaxf(mx1, fmaxf(sa[nt][2], sa[nt][3]));
        }
        mx0 = fmaxf(mx0, __shfl_xor_sync(0xffffffffu, mx0, 1));
        mx0 = fmaxf(mx0, __shfl_xor_sync(0xffffffffu, mx0, 2));
        mx1 = fmaxf(mx1, __shfl_xor_sync(0xffffffffu, mx1, 1));
        mx1 = fmaxf(mx1, __shfl_xor_sync(0xffffffffu, mx1, 2));

        float nm0 = fmaxf(m0, mx0), nm1 = fmaxf(m1, mx1);
        float c0 = __expf(m0 - nm0), c1 = __expf(m1 - nm1);
        m0 = nm0; m1 = nm1;

        float rs0 = 0.f, rs1 = 0.f;
#pragma unroll
        for (int nt = 0; nt < 16; nt++) {
            sa[nt][0] = __expf(sa[nt][0] - m0);
            sa[nt][1] = __expf(sa[nt][1] - m0);
            sa[nt][2] = __expf(sa[nt][2] - m1);
            sa[nt][3] = __expf(sa[nt][3] - m1);
            rs0 += sa[nt][0] + sa[nt][1];
            rs1 += sa[nt][2] + sa[nt][3];
        }
        rs0 += __shfl_xor_sync(0xffffffffu, rs0, 1);
        rs0 += __shfl_xor_sync(0xffffffffu, rs0, 2);
        rs1 += __shfl_xor_sync(0xffffffffu, rs1, 1);
        rs1 += __shfl_xor_sync(0xffffffffu, rs1, 2);
        l0 = l0 * c0 + rs0;
        l1 = l1 * c1 + rs1;
#pragma unroll
        for (int dt = 0; dt < 8; dt++) {
            accO[dt][0] *= c0; accO[dt][1] *= c0;
            accO[dt][2] *= c1; accO[dt][3] *= c1;
        }

        // ---- O += P V (3-term, V via trans ldmatrix) ----
#pragma unroll
        for (int ks = 0; ks < 8; ks++) {
            uint32_t pa_h[4], pa_l[4];
#pragma unroll
            for (int half = 0; half < 2; half++) {
                const float* s4 = sa[2 * ks + half];
                __nv_bfloat16 h0 = __float2bfloat16(s4[0]);
                __nv_bfloat16 h1 = __float2bfloat16(s4[1]);
                __nv_bfloat16 h2 = __float2bfloat16(s4[2]);
                __nv_bfloat16 h3 = __float2bfloat16(s4[3]);
                pa_h[2 * half + 0] = pk_bf2(h0, h1);
                pa_h[2 * half + 1] = pk_bf2(h2, h3);
                pa_l[2 * half + 0] = pk_bf2(
                    __float2bfloat16(s4[0] - __bfloat162float(h0)),
                    __float2bfloat16(s4[1] - __bfloat162float(h1)));
                pa_l[2 * half + 1] = pk_bf2(
                    __float2bfloat16(s4[2] - __bfloat162float(h2)),
                    __float2bfloat16(s4[3] - __bfloat162float(h3)));
            }
#pragma unroll
            for (int vg = 0; vg < 4; vg++) {
                uint32_t vh[4], vl[4];
                uint32_t o = (uint32_t)(((ks * 16 + lv_r) * LDKV + vg * 16 + lv_c) * 2);
                ldm_x4_t(vh, st + AVH + o);
                ldm_x4_t(vl, st + AVL + o);
                mma_bf16(accO[2 * vg],     pa_h, vh);
                mma_bf16(accO[2 * vg],     pa_h, vl);
                mma_bf16(accO[2 * vg],     pa_l, vh);
                mma_bf16(accO[2 * vg + 1], pa_h, vh + 2);
                mma_bf16(accO[2 * vg + 1], pa_h, vl + 2);
                mma_bf16(accO[2 * vg + 1], pa_l, vh + 2);
            }
        }
        __syncthreads();
        attn_issue(kt + 2, qt, sb, base, row, j0);
    }

    // ---- write Yh/Yl ----
    const float il0 = 1.f / l0, il1 = 1.f / l1;
    const int row0 = qt * 128 + q0w + (lane >> 2);
    const int row1 = row0 + 8;
#pragma unroll
    for (int dt = 0; dt < 8; dt++) {
        int col = h * HDim + dt * 8 + (lane & 3) * 2;
        float a0 = accO[dt][0] * il0, a1 = accO[dt][1] * il0;
        float a2 = accO[dt][2] * il1, a3 = accO[dt][3] * il1;
        size_t i0 = (size_t)(b * Seq + row0) * Dim + col;
        size_t i1 = (size_t)(b * Seq + row1) * Dim + col;
        __nv_bfloat16 h0 = __float2bfloat16(a0), h1 = __float2bfloat16(a1);
        __nv_bfloat16 h2 = __float2bfloat16(a2), h3 = __float2bfloat16(a3);
        *(uint32_t*)&g_Yh[i0] = pk_bf2(h0, h1);
        *(uint32_t*)&g_Yl[i0] = pk_bf2(
            __float2bfloat16(a0 - __bfloat162float(h0)),
            __float2bfloat16(a1 - __bfloat162float(h1)));
        *(uint32_t*)&g_Yh[i1] = pk_bf2(h2, h3);
        *(uint32_t*)&g_Yl[i1] = pk_bf2(
            __float2bfloat16(a2 - __bfloat162float(h2)),
            __float2bfloat16(a3 - __bfloat162float(h3)));
    }
}

// ===========================================================================
extern "C" void kernel_launch(void* const* d_in, const int* in_sizes, int n_in,
                              void* d_out, int out_size) {
    const float* x    = (const float*)d_in[0];
    const float* fc   = (const float*)d_in[1];
    // d_in[2] = mask — causality structural, unused
    const float* wqkv = (const float*)d_in[3];
    const float* wo   = (const float*)d_in[4];
    float* out = (float*)d_out;

    float* qkv_ptr = nullptr;
    cudaGetSymbolAddress((void**)&qkv_ptr, g_qkv);
    __nv_bfloat16 *Xh, *Xl, *Wqh, *Wql, *Woh, *Wol, *Yh, *Yl;
    cudaGetSymbolAddress((void**)&Xh, g_Xh);
    cudaGetSymbolAddress((void**)&Xl, g_Xl);
    cudaGetSymbolAddress((void**)&Wqh, g_Wqh);
    cudaGetSymbolAddress((void**)&Wql, g_Wql);
    cudaGetSymbolAddress((void**)&Woh, g_Woh);
    cudaGetSymbolAddress((void**)&Wol, g_Wol);
    cudaGetSymbolAddress((void**)&Yh, g_Yh);
    cudaGetSymbolAddress((void**)&Yl, g_Yl);

    cudaFuncSetAttribute(gemm_bf, cudaFuncAttributeMaxDynamicSharedMemorySize,
                         GEMM_SMEM);
    cudaFuncSetAttribute(attn_bf, cudaFuncAttributeMaxDynamicSharedMemorySize,
                         ATTN_SMEM);

    const int M = Bsz * Seq;  // 4096

    // 0) pre-split inputs
    split_kernel<<<(M * Dim / 4 + 255) / 256, 256>>>(x, Xh, Xl, M * Dim / 4);
    split_kernel<<<(3 * Dim * Dim / 4 + 255) / 256, 256>>>(wqkv, Wqh, Wql,
                                                           3 * Dim * Dim / 4);
    split_kernel<<<(Dim * Dim / 4 + 255) / 256, 256>>>(wo, Woh, Wol,
                                                       Dim * Dim / 4);
    // 1) QKV = X @ Wqkv^T
    {
        dim3 grid(3 * Dim / 128, M / 128);
        gemm_bf<<<grid, 256, GEMM_SMEM>>>(Xh, Xl, Wqh, Wql, qkv_ptr, 3 * Dim);
    }
    // 2) rope + split to per-head planes
    {
        int total = Bsz * Seq * 512;
        rope_split<<<(total + 255) / 256, 256>>>(fc);
    }
    // 3) attention -> Yh/Yl
    {
        dim3 grid(Seq / 128, Bsz * NHead);
        attn_bf<<<grid, 256, ATTN_SMEM>>>();
    }
    // 4) out = Y @ Wo^T
    {
        dim3 grid(Dim / 128, M / 128);
        gemm_bf<<<grid, 256, GEMM_SMEM>>>(Yh, Yl, Woh, Wol, out, Dim);
    }
}

// round 8
// speedup vs baseline: 5.4290x; 1.9999x over previous
#include <cuda_runtime.h>
#include <cuda_fp16.h>
#include <cstdint>
#include <math.h>

#define Bsz   2
#define Seq   2048
#define Dim   1024
#define NHead 16
#define HDim  64

// fp32 QKV scratch
__device__ float g_qkv[Bsz * Seq * 3 * Dim];
// fp16 operands
__device__ __half g_X [4096 * 1024];
__device__ __half g_Wq[3072 * 1024];
__device__ __half g_Wo[1024 * 1024];
// per-(b,h) planes [32][2048][64]
__device__ __half g_Q[32 * 2048 * 64];
__device__ __half g_K[32 * 2048 * 64];
__device__ __half g_V[32 * 2048 * 64];
// attention output fp16
__device__ __half g_Y[4096 * 1024];

// ===========================================================================
// helpers
// ===========================================================================
__device__ __forceinline__ void ldm_x4(uint32_t* r, uint32_t addr) {
    asm volatile("ldmatrix.sync.aligned.m8n8.x4.shared.b16 {%0,%1,%2,%3}, [%4];"
                 : "=r"(r[0]), "=r"(r[1]), "=r"(r[2]), "=r"(r[3]) : "r"(addr));
}
__device__ __forceinline__ void ldm_x4_t(uint32_t* r, uint32_t addr) {
    asm volatile("ldmatrix.sync.aligned.m8n8.x4.trans.shared.b16 {%0,%1,%2,%3}, [%4];"
                 : "=r"(r[0]), "=r"(r[1]), "=r"(r[2]), "=r"(r[3]) : "r"(addr));
}
__device__ __forceinline__ void mma_fp16(float* d, const uint32_t* a,
                                         const uint32_t* b) {
    asm volatile(
        "mma.sync.aligned.m16n8k16.row.col.f32.f16.f16.f32 "
        "{%0,%1,%2,%3}, {%4,%5,%6,%7}, {%8,%9}, {%0,%1,%2,%3};"
        : "+f"(d[0]), "+f"(d[1]), "+f"(d[2]), "+f"(d[3])
        : "r"(a[0]), "r"(a[1]), "r"(a[2]), "r"(a[3]), "r"(b[0]), "r"(b[1]));
}
__device__ __forceinline__ uint32_t smem_u32(const void* p) {
    uint32_t a;
    asm("{ .reg .u64 t; cvta.to.shared.u64 t, %1; cvt.u32.u64 %0, t; }"
        : "=r"(a) : "l"(p));
    return a;
}
__device__ __forceinline__ uint32_t pk_h2(__half a, __half b) {
    __half2 t(a, b);
    return *reinterpret_cast<uint32_t*>(&t);
}
__device__ __forceinline__ void cpa16(uint32_t s, const void* g) {
    asm volatile("cp.async.cg.shared.global [%0], [%1], 16;" :: "r"(s), "l"(g));
}
#define CP_COMMIT() asm volatile("cp.async.commit_group;")
#define CP_WAIT2()  asm volatile("cp.async.wait_group 2;")
#define CP_WAIT1()  asm volatile("cp.async.wait_group 1;")
#define CP_WAIT0()  asm volatile("cp.async.wait_group 0;")

// ===========================================================================
// fp32 -> fp16 convert (vectorized by 4)
// ===========================================================================
__global__ __launch_bounds__(256) void cvt_kernel(const float* __restrict__ src,
                                                  __half* __restrict__ dst,
                                                  int n4) {
    int i = blockIdx.x * blockDim.x + threadIdx.x;
    if (i >= n4) return;
    float4 v = ((const float4*)src)[i];
    ((uint2*)dst)[i] = make_uint2(
        pk_h2(__float2half(v.x), __float2half(v.y)),
        pk_h2(__float2half(v.z), __float2half(v.w)));
}

// ===========================================================================
// rope + scatter to per-(b,h) fp16 planes. thread = (b, s, p), p in [0,512)
// ===========================================================================
__global__ __launch_bounds__(256) void rope_split(const float* __restrict__ fc) {
    int idx = blockIdx.x * blockDim.x + threadIdx.x;
    if (idx >= Bsz * Seq * 512) return;
    int p = idx & 511;
    int s = (idx >> 9) & 2047;
    int b = idx >> 20;
    int h = p >> 5, j = p & 31;
    float c  = fc[s * 64 + j * 2 + 0];
    float sn = fc[s * 64 + j * 2 + 1];
    const float* src = g_qkv + (size_t)(b * Seq + s) * 3 * Dim;
    int d2 = p * 2;

    float qr = src[d2], qi = src[d2 + 1];
    float oqr = (qr * c - qi * sn) * 0.125f;
    float oqi = (qi * c + qr * sn) * 0.125f;
    float kr = src[Dim + d2], ki = src[Dim + d2 + 1];
    float okr = kr * c - ki * sn;
    float oki = ki * c + kr * sn;
    float v0 = src[2 * Dim + d2], v1 = src[2 * Dim + d2 + 1];

    size_t o = ((size_t)(b * NHead + h) * Seq + s) * HDim + 2 * j;
    *(uint32_t*)(g_Q + o) = pk_h2(__float2half(oqr), __float2half(oqi));
    *(uint32_t*)(g_K + o) = pk_h2(__float2half(okr), __float2half(oki));
    *(uint32_t*)(g_V + o) = pk_h2(__float2half(v0),  __float2half(v1));
}

// ===========================================================================
// gemm_h: C[M][N] = A[M][1024] @ B[N][1024]^T, fp16 operands, fp32 out.
// 128x128 tile, BK=32, 256 threads, 3-stage cp.async pipeline, 1-term HMMA.
// ===========================================================================
#define LDSS 40
#define G_ARR (128 * LDSS * 2)       // 10240 B (fp16)
#define G_STAGE (2 * G_ARR)          // 20480 B
#define GEMM_SMEM (3 * G_STAGE)      // 61440 B
#define GOA 0
#define GOB G_ARR
#define G_NIT 32

__device__ __forceinline__ void gemm_issue(
    int it, uint32_t sb, int bm, int bn, int row, int half,
    const __half* A, const __half* B) {
    if (it < G_NIT) {
        uint32_t st = sb + (it % 3) * G_STAGE;
        int k0 = it * 32;
        size_t ga = (size_t)(bm + row) * 1024 + k0 + half * 16;
        size_t gb = (size_t)(bn + row) * 1024 + k0 + half * 16;
        uint32_t so = row * (LDSS * 2) + half * 32;
        cpa16(st + GOA + so,      A + ga);
        cpa16(st + GOA + so + 16, A + ga + 8);
        cpa16(st + GOB + so,      B + gb);
        cpa16(st + GOB + so + 16, B + gb + 8);
    }
    CP_COMMIT();
}

__global__ __launch_bounds__(256) void gemm_h(
    const __half* __restrict__ A, const __half* __restrict__ B,
    float* __restrict__ C, int N) {
    extern __shared__ char smem[];
    const uint32_t sb = smem_u32(smem);
    const int t = threadIdx.x, lane = t & 31, wid = t >> 5;
    const int wm = (wid & 1) * 64, wn = (wid >> 1) * 32;
    const int bm = blockIdx.y * 128, bn = blockIdx.x * 128;
    const int row = t >> 1, half = t & 1;

    float d[4][4][4];
#pragma unroll
    for (int mi = 0; mi < 4; mi++)
#pragma unroll
        for (int nj = 0; nj < 4; nj++)
#pragma unroll
            for (int e = 0; e < 4; e++) d[mi][nj][e] = 0.f;

    gemm_issue(0, sb, bm, bn, row, half, A, B);
    gemm_issue(1, sb, bm, bn, row, half, A, B);
    gemm_issue(2, sb, bm, bn, row, half, A, B);

    for (int it = 0; it < G_NIT; it++) {
        CP_WAIT2();
        __syncthreads();
        const uint32_t st = sb + (it % 3) * G_STAGE;
#pragma unroll
        for (int ks = 0; ks < 2; ks++) {
            const int k0 = ks * 16;
            uint32_t af[4][4];
            const int arow = wm + (lane & 15);
            const int acol = k0 + ((lane & 16) ? 8 : 0);
#pragma unroll
            for (int mi = 0; mi < 4; mi++)
                ldm_x4(af[mi], st + GOA +
                       (uint32_t)(((arow + mi * 16) * LDSS + acol) * 2));
            uint32_t bf[2][4];
            const int brow = wn + (lane & 7) + ((lane & 16) >> 1);
            const int bcol = k0 + ((lane & 8) ? 8 : 0);
#pragma unroll
            for (int nb = 0; nb < 2; nb++)
                ldm_x4(bf[nb], st + GOB +
                       (uint32_t)(((brow + nb * 16) * LDSS + bcol) * 2));
#pragma unroll
            for (int mi = 0; mi < 4; mi++)
#pragma unroll
                for (int nj = 0; nj < 4; nj++)
                    mma_fp16(d[mi][nj], af[mi], &bf[nj >> 1][(nj & 1) * 2]);
        }
        __syncthreads();
        gemm_issue(it + 3, sb, bm, bn, row, half, A, B);
    }

#pragma unroll
    for (int mi = 0; mi < 4; mi++)
#pragma unroll
        for (int nj = 0; nj < 4; nj++) {
            int r = bm + wm + mi * 16 + (lane >> 2);
            int c = bn + wn + nj * 8 + (lane & 3) * 2;
            *(float2*)&C[(size_t)r * N + c] =
                make_float2(d[mi][nj][0], d[mi][nj][1]);
            *(float2*)&C[(size_t)(r + 8) * N + c] =
                make_float2(d[mi][nj][2], d[mi][nj][3]);
        }
}

// ===========================================================================
// attention: 128 q-rows x (b,h); k-tile 128; cp.async double-buffered K/V;
// fp16 single-term HMMA; V row-major + ldmatrix.trans; online softmax.
// ===========================================================================
#define LDKV 72
#define A_ARR (128 * LDKV * 2)       // 18432 B
#define A_STAGE (2 * A_ARR)          // 36864 B
#define ATTN_SMEM (2 * A_STAGE)      // 73728 B
#define AK 0
#define AV A_ARR

__device__ __forceinline__ void attn_issue(int kt, int qt, uint32_t sb,
                                           size_t base, int row, int j0) {
    if (kt <= qt) {
        uint32_t st = sb + (kt & 1) * A_STAGE;
        size_t g = base + (size_t)(kt * 128 + row) * 64 + j0 * 8;
        uint32_t so = row * (LDKV * 2) + j0 * 16;
#pragma unroll
        for (int c = 0; c < 4; c++) {
            cpa16(st + AK + so + c * 16, g_K + g + c * 8);
            cpa16(st + AV + so + c * 16, g_V + g + c * 8);
        }
    }
    CP_COMMIT();
}

__global__ __launch_bounds__(256, 1) void attn_h() {
    extern __shared__ char smc[];
    const uint32_t sb = smem_u32(smc);
    const int tid = threadIdx.x, lane = tid & 31, w = tid >> 5;
    const int qt = blockIdx.x, bh = blockIdx.y;
    const int b = bh >> 4, h = bh & 15;
    const size_t base = (size_t)bh * Seq * HDim;
    const int q0w = w * 16;
    const int row = tid >> 1, j0 = (tid & 1) * 4;

    const int la_r = lane & 15;
    const int la_c = (lane & 16) ? 8 : 0;
    const int lb_r = (lane & 7) + ((lane & 16) >> 1);
    const int lb_c = (lane & 8) ? 8 : 0;

    // ---- stage Q into buf0 K region, extract frags ----
    {
        size_t gq = base + (size_t)(qt * 128 + row) * 64 + j0 * 8;
        uint32_t so = row * (LDKV * 2) + j0 * 16;
#pragma unroll
        for (int c = 0; c < 4; c++)
            cpa16(sb + AK + so + c * 16, g_Q + gq + c * 8);
    }
    CP_COMMIT();
    CP_WAIT0();
    __syncthreads();
    uint32_t qf[4][4];
#pragma unroll
    for (int ks = 0; ks < 4; ks++)
        ldm_x4(qf[ks], sb + AK +
               (uint32_t)(((q0w + la_r) * LDKV + ks * 16 + la_c) * 2));
    __syncthreads();

    float accO[8][4];
#pragma unroll
    for (int i = 0; i < 8; i++)
#pragma unroll
        for (int e = 0; e < 4; e++) accO[i][e] = 0.f;
    float m0 = -1e30f, m1 = -1e30f, l0 = 0.f, l1 = 0.f;

    attn_issue(0, qt, sb, base, row, j0);
    attn_issue(1, qt, sb, base, row, j0);

    for (int kt = 0; kt <= qt; kt++) {
        CP_WAIT1();
        __syncthreads();
        const uint32_t st = sb + (kt & 1) * A_STAGE;

        // ---- S = Q K^T ----
        float sa[16][4];
#pragma unroll
        for (int i = 0; i < 16; i++)
#pragma unroll
            for (int e = 0; e < 4; e++) sa[i][e] = 0.f;

#pragma unroll
        for (int ks = 0; ks < 4; ks++) {
#pragma unroll
            for (int bg = 0; bg < 8; bg++) {
                uint32_t kf[4];
                ldm_x4(kf, st + AK +
                       (uint32_t)(((bg * 16 + lb_r) * LDKV + ks * 16 + lb_c) * 2));
                mma_fp16(sa[2 * bg],     qf[ks], kf);
                mma_fp16(sa[2 * bg + 1], qf[ks], kf + 2);
            }
        }

        // ---- causal mask on diagonal tile ----
        const int r0 = q0w + (lane >> 2), r1 = r0 + 8;
        if (kt == qt) {
#pragma unroll
            for (int nt = 0; nt < 16; nt++) {
                int c = nt * 8 + (lane & 3) * 2;
                if (c > r0)     sa[nt][0] = -1e30f;
                if (c + 1 > r0) sa[nt][1] = -1e30f;
                if (c > r1)     sa[nt][2] = -1e30f;
                if (c + 1 > r1) sa[nt][3] = -1e30f;
            }
        }

        // ---- online softmax ----
        float mx0 = -1e30f, mx1 = -1e30f;
#pragma unroll
        for (int nt = 0; nt < 16; nt++) {
            mx0 = fmaxf(mx0, fmaxf(sa[nt][0], sa[nt][1]));
            mx1 = fmaxf(mx1, fmaxf(sa[nt][2], sa[nt][3]));
        }
        mx0 = fmaxf(mx0, __shfl_xor_sync(0xffffffffu, mx0, 1));
        mx0 = fmaxf(mx0, __shfl_xor_sync(0xffffffffu, mx0, 2));
        mx1 = fmaxf(mx1, __shfl_xor_sync(0xffffffffu, mx1, 1));
        mx1 = fmaxf(mx1, __shfl_xor_sync(0xffffffffu, mx1, 2));

        float nm0 = fmaxf(m0, mx0), nm1 = fmaxf(m1, mx1);
        float c0 = __expf(m0 - nm0), c1 = __expf(m1 - nm1);
        m0 = nm0; m1 = nm1;

        float rs0 = 0.f, rs1 = 0.f;
#pragma unroll
        for (int nt = 0; nt < 16; nt++) {
            sa[nt][0] = __expf(sa[nt][0] - m0);
            sa[nt][1] = __expf(sa[nt][1] - m0);
            sa[nt][2] = __expf(sa[nt][2] - m1);
            sa[nt][3] = __expf(sa[nt][3] - m1);
            rs0 += sa[nt][0] + sa[nt][1];
            rs1 += sa[nt][2] + sa[nt][3];
        }
        rs0 += __shfl_xor_sync(0xffffffffu, rs0, 1);
        rs0 += __shfl_xor_sync(0xffffffffu, rs0, 2);
        rs1 += __shfl_xor_sync(0xffffffffu, rs1, 1);
        rs1 += __shfl_xor_sync(0xffffffffu, rs1, 2);
        l0 = l0 * c0 + rs0;
        l1 = l1 * c1 + rs1;
#pragma unroll
        for (int dt = 0; dt < 8; dt++) {
            accO[dt][0] *= c0; accO[dt][1] *= c0;
            accO[dt][2] *= c1; accO[dt][3] *= c1;
        }

        // ---- O += P V (V via trans ldmatrix) ----
#pragma unroll
        for (int ks = 0; ks < 8; ks++) {
            uint32_t pa[4];
#pragma unroll
            for (int hf = 0; hf < 2; hf++) {
                const float* s4 = sa[2 * ks + hf];
                pa[2 * hf + 0] = pk_h2(__float2half(s4[0]), __float2half(s4[1]));
                pa[2 * hf + 1] = pk_h2(__float2half(s4[2]), __float2half(s4[3]));
            }
#pragma unroll
            for (int vg = 0; vg < 4; vg++) {
                uint32_t vf[4];
                ldm_x4_t(vf, st + AV +
                         (uint32_t)(((ks * 16 + la_r) * LDKV + vg * 16 + la_c) * 2));
                mma_fp16(accO[2 * vg],     pa, vf);
                mma_fp16(accO[2 * vg + 1], pa, vf + 2);
            }
        }
        __syncthreads();
        attn_issue(kt + 2, qt, sb, base, row, j0);
    }

    // ---- write Y (fp16) ----
    const float il0 = 1.f / l0, il1 = 1.f / l1;
    const int row0 = qt * 128 + q0w + (lane >> 2);
    const int row1 = row0 + 8;
#pragma unroll
    for (int dt = 0; dt < 8; dt++) {
        int col = h * HDim + dt * 8 + (lane & 3) * 2;
        size_t i0 = (size_t)(b * Seq + row0) * Dim + col;
        size_t i1 = (size_t)(b * Seq + row1) * Dim + col;
        *(uint32_t*)&g_Y[i0] = pk_h2(__float2half(accO[dt][0] * il0),
                                     __float2half(accO[dt][1] * il0));
        *(uint32_t*)&g_Y[i1] = pk_h2(__float2half(accO[dt][2] * il1),
                                     __float2half(accO[dt][3] * il1));
    }
}

// ===========================================================================
extern "C" void kernel_launch(void* const* d_in, const int* in_sizes, int n_in,
                              void* d_out, int out_size) {
    const float* x    = (const float*)d_in[0];
    const float* fc   = (const float*)d_in[1];
    // d_in[2] = mask — causality structural, unused
    const float* wqkv = (const float*)d_in[3];
    const float* wo   = (const float*)d_in[4];
    float* out = (float*)d_out;

    float* qkv_ptr = nullptr;
    cudaGetSymbolAddress((void**)&qkv_ptr, g_qkv);
    __half *X, *Wq, *Wo_, *Y;
    cudaGetSymbolAddress((void**)&X,   g_X);
    cudaGetSymbolAddress((void**)&Wq,  g_Wq);
    cudaGetSymbolAddress((void**)&Wo_, g_Wo);
    cudaGetSymbolAddress((void**)&Y,   g_Y);

    cudaFuncSetAttribute(gemm_h, cudaFuncAttributeMaxDynamicSharedMemorySize,
                         GEMM_SMEM);
    cudaFuncSetAttribute(attn_h, cudaFuncAttributeMaxDynamicSharedMemorySize,
                         ATTN_SMEM);

    const int M = Bsz * Seq;  // 4096

    // 0) convert inputs to fp16
    cvt_kernel<<<(M * Dim / 4 + 255) / 256, 256>>>(x, X, M * Dim / 4);
    cvt_kernel<<<(3 * Dim * Dim / 4 + 255) / 256, 256>>>(wqkv, Wq,
                                                         3 * Dim * Dim / 4);
    cvt_kernel<<<(Dim * Dim / 4 + 255) / 256, 256>>>(wo, Wo_, Dim * Dim / 4);
    // 1) QKV = X @ Wqkv^T
    {
        dim3 grid(3 * Dim / 128, M / 128);
        gemm_h<<<grid, 256, GEMM_SMEM>>>(X, Wq, qkv_ptr, 3 * Dim);
    }
    // 2) rope + scatter to per-head fp16 planes
    {
        int total = Bsz * Seq * 512;
        rope_split<<<(total + 255) / 256, 256>>>(fc);
    }
    // 3) attention -> Y (fp16)
    {
        dim3 grid(Seq / 128, Bsz * NHead);
        attn_h<<<grid, 256, ATTN_SMEM>>>();
    }
    // 4) out = Y @ Wo^T
    {
        dim3 grid(Dim / 128, M / 128);
        gemm_h<<<grid, 256, GEMM_SMEM>>>(Y, Wo_, out, Dim);
    }
}

// round 11
// speedup vs baseline: 5.6946x; 1.0489x over previous
#include <cuda_runtime.h>
#include <cuda_fp16.h>
#include <cstdint>
#include <math.h>

#define Bsz   2
#define Seq   2048
#define Dim   1024
#define NHead 16
#define HDim  64

// fp16 operands
__device__ __half g_X [4096 * 1024];
__device__ __half g_Wq[3072 * 1024];
__device__ __half g_Wo[1024 * 1024];
// per-(b,h) planes [32][2048][64]
__device__ __half g_Q[32 * 2048 * 64];
__device__ __half g_K[32 * 2048 * 64];
__device__ __half g_V[32 * 2048 * 64];
// attention output fp16
__device__ __half g_Y[4096 * 1024];

// ===========================================================================
// helpers
// ===========================================================================
__device__ __forceinline__ void ldm_x4(uint32_t* r, uint32_t addr) {
    asm volatile("ldmatrix.sync.aligned.m8n8.x4.shared.b16 {%0,%1,%2,%3}, [%4];"
                 : "=r"(r[0]), "=r"(r[1]), "=r"(r[2]), "=r"(r[3]) : "r"(addr));
}
__device__ __forceinline__ void ldm_x4_t(uint32_t* r, uint32_t addr) {
    asm volatile("ldmatrix.sync.aligned.m8n8.x4.trans.shared.b16 {%0,%1,%2,%3}, [%4];"
                 : "=r"(r[0]), "=r"(r[1]), "=r"(r[2]), "=r"(r[3]) : "r"(addr));
}
__device__ __forceinline__ void mma_fp16(float* d, const uint32_t* a,
                                         const uint32_t* b) {
    asm volatile(
        "mma.sync.aligned.m16n8k16.row.col.f32.f16.f16.f32 "
        "{%0,%1,%2,%3}, {%4,%5,%6,%7}, {%8,%9}, {%0,%1,%2,%3};"
        : "+f"(d[0]), "+f"(d[1]), "+f"(d[2]), "+f"(d[3])
        : "r"(a[0]), "r"(a[1]), "r"(a[2]), "r"(a[3]), "r"(b[0]), "r"(b[1]));
}
__device__ __forceinline__ uint32_t smem_u32(const void* p) {
    uint32_t a;
    asm("{ .reg .u64 t; cvta.to.shared.u64 t, %1; cvt.u32.u64 %0, t; }"
        : "=r"(a) : "l"(p));
    return a;
}
__device__ __forceinline__ uint32_t pk_h2(__half a, __half b) {
    __half2 t(a, b);
    return *reinterpret_cast<uint32_t*>(&t);
}
__device__ __forceinline__ void cpa16(uint32_t s, const void* g) {
    asm volatile("cp.async.cg.shared.global [%0], [%1], 16;" :: "r"(s), "l"(g));
}
#define CP_COMMIT() asm volatile("cp.async.commit_group;")
#define CP_WAIT2()  asm volatile("cp.async.wait_group 2;")
#define CP_WAIT0()  asm volatile("cp.async.wait_group 0;")

// ===========================================================================
// fp32 -> fp16 convert (vectorized by 4)
// ===========================================================================
__global__ __launch_bounds__(256) void cvt_kernel(const float* __restrict__ src,
                                                  __half* __restrict__ dst,
                                                  int n4) {
    int i = blockIdx.x * blockDim.x + threadIdx.x;
    if (i >= n4) return;
    float4 v = ((const float4*)src)[i];
    ((uint2*)dst)[i] = make_uint2(
        pk_h2(__float2half(v.x), __float2half(v.y)),
        pk_h2(__float2half(v.z), __float2half(v.w)));
}

// ===========================================================================
// fused QKV epilogue store: rope on q/k, scale q, scatter to fp16 planes.
// col is even; (col, col+1) is a rotary pair.
// ===========================================================================
__device__ __forceinline__ void qkv_store(int row, int col, float v0, float v1,
                                          const float* __restrict__ fc) {
    int b = row >> 11, s = row & 2047;
    int sec = col >> 10;            // 0=q, 1=k, 2=v
    int cm  = col & 1023;
    int h = cm >> 6, dd = cm & 63;
    size_t o = ((size_t)(b * NHead + h) * Seq + s) * HDim + dd;
    if (sec == 2) {
        *(uint32_t*)(g_V + o) = pk_h2(__float2half(v0), __float2half(v1));
    } else {
        int j = dd >> 1;
        float c  = fc[s * 64 + j * 2 + 0];
        float sn = fc[s * 64 + j * 2 + 1];
        float r0 = v0 * c - v1 * sn;
        float r1 = v1 * c + v0 * sn;
        if (sec == 0) {
            r0 *= 0.125f; r1 *= 0.125f;
            *(uint32_t*)(g_Q + o) = pk_h2(__float2half(r0), __float2half(r1));
        } else {
            *(uint32_t*)(g_K + o) = pk_h2(__float2half(r0), __float2half(r1));
        }
    }
}

// ===========================================================================
// gemm_h: C[M][N] = A[M][1024] @ B[N][1024]^T, fp16 operands, fp32 accum.
// mode 0: store fp32 C.  mode 1: fused rope+scatter (QKV).
// 128x128 tile, BK=32, 256 threads, 3-stage cp.async pipeline.
// ===========================================================================
#define LDSS 40
#define G_ARR (128 * LDSS * 2)       // 10240 B (fp16)
#define G_STAGE (2 * G_ARR)          // 20480 B
#define GEMM_SMEM (3 * G_STAGE)      // 61440 B
#define GOA 0
#define GOB G_ARR
#define G_NIT 32

__device__ __forceinline__ void gemm_issue(
    int it, uint32_t sb, int bm, int bn, int row, int half,
    const __half* A, const __half* B) {
    if (it < G_NIT) {
        uint32_t st = sb + (it % 3) * G_STAGE;
        int k0 = it * 32;
        size_t ga = (size_t)(bm + row) * 1024 + k0 + half * 16;
        size_t gb = (size_t)(bn + row) * 1024 + k0 + half * 16;
        uint32_t so = row * (LDSS * 2) + half * 32;
        cpa16(st + GOA + so,      A + ga);
        cpa16(st + GOA + so + 16, A + ga + 8);
        cpa16(st + GOB + so,      B + gb);
        cpa16(st + GOB + so + 16, B + gb + 8);
    }
    CP_COMMIT();
}

__global__ __launch_bounds__(256) void gemm_h(
    const __half* __restrict__ A, const __half* __restrict__ B,
    float* __restrict__ C, int N, const float* __restrict__ fc, int mode) {
    extern __shared__ char smem[];
    const uint32_t sb = smem_u32(smem);
    const int t = threadIdx.x, lane = t & 31, wid = t >> 5;
    const int wm = (wid & 1) * 64, wn = (wid >> 1) * 32;
    const int bm = blockIdx.y * 128, bn = blockIdx.x * 128;
    const int row = t >> 1, half = t & 1;

    float d[4][4][4];
#pragma unroll
    for (int mi = 0; mi < 4; mi++)
#pragma unroll
        for (int nj = 0; nj < 4; nj++)
#pragma unroll
            for (int e = 0; e < 4; e++) d[mi][nj][e] = 0.f;

    gemm_issue(0, sb, bm, bn, row, half, A, B);
    gemm_issue(1, sb, bm, bn, row, half, A, B);
    gemm_issue(2, sb, bm, bn, row, half, A, B);

    for (int it = 0; it < G_NIT; it++) {
        CP_WAIT2();
        __syncthreads();
        const uint32_t st = sb + (it % 3) * G_STAGE;
#pragma unroll
        for (int ks = 0; ks < 2; ks++) {
            const int k0 = ks * 16;
            uint32_t af[4][4];
            const int arow = wm + (lane & 15);
            const int acol = k0 + ((lane & 16) ? 8 : 0);
#pragma unroll
            for (int mi = 0; mi < 4; mi++)
                ldm_x4(af[mi], st + GOA +
                       (uint32_t)(((arow + mi * 16) * LDSS + acol) * 2));
            uint32_t bf[2][4];
            const int brow = wn + (lane & 7) + ((lane & 16) >> 1);
            const int bcol = k0 + ((lane & 8) ? 8 : 0);
#pragma unroll
            for (int nb = 0; nb < 2; nb++)
                ldm_x4(bf[nb], st + GOB +
                       (uint32_t)(((brow + nb * 16) * LDSS + bcol) * 2));
#pragma unroll
            for (int mi = 0; mi < 4; mi++)
#pragma unroll
                for (int nj = 0; nj < 4; nj++)
                    mma_fp16(d[mi][nj], af[mi], &bf[nj >> 1][(nj & 1) * 2]);
        }
        __syncthreads();
        gemm_issue(it + 3, sb, bm, bn, row, half, A, B);
    }

    if (mode == 0) {
#pragma unroll
        for (int mi = 0; mi < 4; mi++)
#pragma unroll
            for (int nj = 0; nj < 4; nj++) {
                int r = bm + wm + mi * 16 + (lane >> 2);
                int c = bn + wn + nj * 8 + (lane & 3) * 2;
                *(float2*)&C[(size_t)r * N + c] =
                    make_float2(d[mi][nj][0], d[mi][nj][1]);
                *(float2*)&C[(size_t)(r + 8) * N + c] =
                    make_float2(d[mi][nj][2], d[mi][nj][3]);
            }
    } else {
#pragma unroll
        for (int mi = 0; mi < 4; mi++)
#pragma unroll
            for (int nj = 0; nj < 4; nj++) {
                int r = bm + wm + mi * 16 + (lane >> 2);
                int c = bn + wn + nj * 8 + (lane & 3) * 2;
                qkv_store(r,     c, d[mi][nj][0], d[mi][nj][1], fc);
                qkv_store(r + 8, c, d[mi][nj][2], d[mi][nj][3], fc);
            }
    }
}

// ===========================================================================
// attention: 128 q-rows x (b,h); k-tile 64; 3-stage cp.async; 2 CTAs/SM;
// fp16 HMMA; V row-major + ldmatrix.trans; online softmax.
// ===========================================================================
#define LDKV 72
#define A_K (64 * LDKV * 2)          // 9216 B
#define A_STAGE (2 * A_K)            // 18432 B (K + V)
#define ATTN_SMEM (3 * A_STAGE)      // 55296 B
#define AK 0
#define AV A_K

__device__ __forceinline__ void attn_issue(int kt, int nkt, uint32_t sb,
                                           size_t base, int row4, int j2) {
    if (kt < nkt) {
        uint32_t st = sb + (kt % 3) * A_STAGE;
        size_t g = base + (size_t)(kt * 64 + row4) * 64 + j2 * 16;
        uint32_t so = row4 * (LDKV * 2) + j2 * 32;
        cpa16(st + AK + so,      g_K + g);
        cpa16(st + AK + so + 16, g_K + g + 8);
        cpa16(st + AV + so,      g_V + g);
        cpa16(st + AV + so + 16, g_V + g + 8);
    }
    CP_COMMIT();
}

__global__ __launch_bounds__(256, 2) void attn_h() {
    extern __shared__ char smc[];
    const uint32_t sb = smem_u32(smc);
    const int tid = threadIdx.x, lane = tid & 31, w = tid >> 5;
    const int qt = (int)gridDim.x - 1 - (int)blockIdx.x;   // heavy tiles first
    const int bh = blockIdx.y;
    const int b = bh >> 4, h = bh & 15;
    const size_t base = (size_t)bh * Seq * HDim;
    const int q0w = w * 16;
    const int nkt = 2 * (qt + 1);
    const int row4 = tid >> 2, j2 = tid & 3;

    const int la_r = lane & 15;
    const int la_c = (lane & 16) ? 8 : 0;
    const int lb_r = (lane & 7) + ((lane & 16) >> 1);
    const int lb_c = (lane & 8) ? 8 : 0;

    // ---- stage Q (128 rows) into stage-0 region, extract frags ----
    {
        int row2 = tid >> 1, j1 = tid & 1;
        size_t gq = base + (size_t)(qt * 128 + row2) * 64 + j1 * 32;
        uint32_t so = row2 * (LDKV * 2) + j1 * 64;
#pragma unroll
        for (int c = 0; c < 4; c++)
            cpa16(sb + so + c * 16, g_Q + gq + c * 8);
    }
    CP_COMMIT();
    CP_WAIT0();
    __syncthreads();
    uint32_t qf[4][4];
#pragma unroll
    for (int ks = 0; ks < 4; ks++)
        ldm_x4(qf[ks], sb +
               (uint32_t)(((q0w + la_r) * LDKV + ks * 16 + la_c) * 2));
    __syncthreads();

    float accO[8][4];
#pragma unroll
    for (int i = 0; i < 8; i++)
#pragma unroll
        for (int e = 0; e < 4; e++) accO[i][e] = 0.f;
    float m0 = -1e30f, m1 = -1e30f, l0 = 0.f, l1 = 0.f;

    attn_issue(0, nkt, sb, base, row4, j2);
    attn_issue(1, nkt, sb, base, row4, j2);
    attn_issue(2, nkt, sb, base, row4, j2);

    const int r0 = qt * 128 + q0w + (lane >> 2), r1 = r0 + 8;

    for (int kt = 0; kt < nkt; kt++) {
        CP_WAIT2();
        __syncthreads();
        const uint32_t st = sb + (kt % 3) * A_STAGE;

        // ---- S = Q K^T (64 cols) ----
        float sa[8][4];
#pragma unroll
        for (int i = 0; i < 8; i++)
#pragma unroll
            for (int e = 0; e < 4; e++) sa[i][e] = 0.f;

#pragma unroll
        for (int ks = 0; ks < 4; ks++) {
#pragma unroll
            for (int bg = 0; bg < 4; bg++) {
                uint32_t kf[4];
                ldm_x4(kf, st + AK +
                       (uint32_t)(((bg * 16 + lb_r) * LDKV + ks * 16 + lb_c) * 2));
                mma_fp16(sa[2 * bg],     qf[ks], kf);
                mma_fp16(sa[2 * bg + 1], qf[ks], kf + 2);
            }
        }

        // ---- causal mask (only tiles overlapping the diagonal) ----
        if (kt >= 2 * qt) {
            const int kb = kt * 64;
#pragma unroll
            for (int nt = 0; nt < 8; nt++) {
                int c = kb + nt * 8 + (lane & 3) * 2;
                if (c > r0)     sa[nt][0] = -1e30f;
                if (c + 1 > r0) sa[nt][1] = -1e30f;
                if (c > r1)     sa[nt][2] = -1e30f;
                if (c + 1 > r1) sa[nt][3] = -1e30f;
            }
        }

        // ---- online softmax ----
        float mx0 = -1e30f, mx1 = -1e30f;
#pragma unroll
        for (int nt = 0; nt < 8; nt++) {
            mx0 = fmaxf(mx0, fmaxf(sa[nt][0], sa[nt][1]));
            mx1 = fmaxf(mx1, fmaxf(sa[nt][2], sa[nt][3]));
        }
        mx0 = fmaxf(mx0, __shfl_xor_sync(0xffffffffu, mx0, 1));
        mx0 = fmaxf(mx0, __shfl_xor_sync(0xffffffffu, mx0, 2));
        mx1 = fmaxf(mx1, __shfl_xor_sync(0xffffffffu, mx1, 1));
        mx1 = fmaxf(mx1, __shfl_xor_sync(0xffffffffu, mx1, 2));

        float nm0 = fmaxf(m0, mx0), nm1 = fmaxf(m1, mx1);
        float c0 = __expf(m0 - nm0), c1 = __expf(m1 - nm1);
        m0 = nm0; m1 = nm1;

        float rs0 = 0.f, rs1 = 0.f;
#pragma unroll
        for (int nt = 0; nt < 8; nt++) {
            sa[nt][0] = __expf(sa[nt][0] - m0);
            sa[nt][1] = __expf(sa[nt][1] - m0);
            sa[nt][2] = __expf(sa[nt][2] - m1);
            sa[nt][3] = __expf(sa[nt][3] - m1);
            rs0 += sa[nt][0] + sa[nt][1];
            rs1 += sa[nt][2] + sa[nt][3];
        }
        rs0 += __shfl_xor_sync(0xffffffffu, rs0, 1);
        rs0 += __shfl_xor_sync(0xffffffffu, rs0, 2);
        rs1 += __shfl_xor_sync(0xffffffffu, rs1, 1);
        rs1 += __shfl_xor_sync(0xffffffffu, rs1, 2);
        l0 = l0 * c0 + rs0;
        l1 = l1 * c1 + rs1;
#pragma unroll
        for (int dt = 0; dt < 8; dt++) {
            accO[dt][0] *= c0; accO[dt][1] *= c0;
            accO[dt][2] *= c1; accO[dt][3] *= c1;
        }

        // ---- O += P V (V via trans ldmatrix) ----
#pragma unroll
        for (int ks = 0; ks < 4; ks++) {
            uint32_t pa[4];
#pragma unroll
            for (int hf = 0; hf < 2; hf++) {
                const float* s4 = sa[2 * ks + hf];
                pa[2 * hf + 0] = pk_h2(__float2half(s4[0]), __float2half(s4[1]));
                pa[2 * hf + 1] = pk_h2(__float2half(s4[2]), __float2half(s4[3]));
            }
#pragma unroll
            for (int vg = 0; vg < 4; vg++) {
                uint32_t vf[4];
                ldm_x4_t(vf, st + AV +
                         (uint32_t)(((ks * 16 + la_r) * LDKV + vg * 16 + la_c) * 2));
                mma_fp16(accO[2 * vg],     pa, vf);
                mma_fp16(accO[2 * vg + 1], pa, vf + 2);
            }
        }
        __syncthreads();
        attn_issue(kt + 3, nkt, sb, base, row4, j2);
    }

    // ---- write Y (fp16) ----
    const float il0 = 1.f / l0, il1 = 1.f / l1;
    const int row0 = qt * 128 + q0w + (lane >> 2);
    const int row1 = row0 + 8;
#pragma unroll
    for (int dt = 0; dt < 8; dt++) {
        int col = h * HDim + dt * 8 + (lane & 3) * 2;
        size_t i0 = (size_t)(b * Seq + row0) * Dim + col;
        size_t i1 = (size_t)(b * Seq + row1) * Dim + col;
        *(uint32_t*)&g_Y[i0] = pk_h2(__float2half(accO[dt][0] * il0),
                                     __float2half(accO[dt][1] * il0));
        *(uint32_t*)&g_Y[i1] = pk_h2(__float2half(accO[dt][2] * il1),
                                     __float2half(accO[dt][3] * il1));
    }
}

// ===========================================================================
extern "C" void kernel_launch(void* const* d_in, const int* in_sizes, int n_in,
                              void* d_out, int out_size) {
    const float* x    = (const float*)d_in[0];
    const float* fc   = (const float*)d_in[1];
    // d_in[2] = mask — causality structural, unused
    const float* wqkv = (const float*)d_in[3];
    const float* wo   = (const float*)d_in[4];
    float* out = (float*)d_out;

    __half *X, *Wq, *Wo_, *Y;
    cudaGetSymbolAddress((void**)&X,   g_X);
    cudaGetSymbolAddress((void**)&Wq,  g_Wq);
    cudaGetSymbolAddress((void**)&Wo_, g_Wo);
    cudaGetSymbolAddress((void**)&Y,   g_Y);

    cudaFuncSetAttribute(gemm_h, cudaFuncAttributeMaxDynamicSharedMemorySize,
                         GEMM_SMEM);
    cudaFuncSetAttribute(attn_h, cudaFuncAttributeMaxDynamicSharedMemorySize,
                         ATTN_SMEM);

    const int M = Bsz * Seq;  // 4096

    // 0) convert inputs to fp16
    cvt_kernel<<<(M * Dim / 4 + 255) / 256, 256>>>(x, X, M * Dim / 4);
    cvt_kernel<<<(3 * Dim * Dim / 4 + 255) / 256, 256>>>(wqkv, Wq,
                                                         3 * Dim * Dim / 4);
    cvt_kernel<<<(Dim * Dim / 4 + 255) / 256, 256>>>(wo, Wo_, Dim * Dim / 4);
    // 1) QKV gemm with fused rope + plane scatter
    {
        dim3 grid(3 * Dim / 128, M / 128);
        gemm_h<<<grid, 256, GEMM_SMEM>>>(X, Wq, out /*unused*/, 3 * Dim, fc, 1);
    }
    // 2) attention -> Y (fp16)
    {
        dim3 grid(Seq / 128, Bsz * NHead);
        attn_h<<<grid, 256, ATTN_SMEM>>>();
    }
    // 3) out = Y @ Wo^T
    {
        dim3 grid(Dim / 128, M / 128);
        gemm_h<<<grid, 256, GEMM_SMEM>>>(Y, Wo_, out, Dim, nullptr, 0);
    }
}